// round 1
// baseline (speedup 1.0000x reference)
#include <cuda_runtime.h>
#include <cstdint>

#define E_ 8
#define D_ 1024
#define H_ 4096
#define O_ 1024
#define B_ 4096
#define MAXROWS 9216          // 8192 rows + per-expert padding to 128, <= 72 tiles
#define NTILES  72            // MAXROWS / 128

// ---------------- static device scratch (no allocations allowed) ----------------
__device__ float g_h[(size_t)MAXROWS * H_];   // GELU(x@W1+b1) per (token,expert) row
__device__ int   g_tok[MAXROWS];              // token index per row
__device__ float g_wgt[MAXROWS];              // router weight per row (0 for pads)
__device__ int   g_counts[E_];                // tokens routed to each expert
__device__ int   g_tile_expert[NTILES];       // expert per 128-row tile (-1 = unused)
__device__ float g_probs[(size_t)B_ * E_];    // softmax probs (for aux loss)
__device__ int   g_topk[B_ * 2];
__device__ float g_topw[B_ * 2];

// ---------------- helpers ----------------
__device__ __forceinline__ uint32_t f2tf(float f) {
    uint32_t u;
    asm("cvt.rna.tf32.f32 %0, %1;" : "=r"(u) : "f"(f));
    return u;
}
__device__ __forceinline__ void cp16(void* s, const void* g) {
    uint32_t sa = (uint32_t)__cvta_generic_to_shared(s);
    asm volatile("cp.async.cg.shared.global [%0], [%1], 16;\n" :: "r"(sa), "l"(g));
}
#define CP_COMMIT() asm volatile("cp.async.commit_group;\n")

// ---------------- init: zero output + counters ----------------
__global__ void init_kernel(float* __restrict__ out) {
    size_t i = (size_t)blockIdx.x * blockDim.x + threadIdx.x;   // B_*O_/4 float4s
    float4 z = make_float4(0.f, 0.f, 0.f, 0.f);
    ((float4*)out)[i] = z;
    if (blockIdx.x == 0 && threadIdx.x < E_) g_counts[threadIdx.x] = 0;
}

// ---------------- router: 1 warp per token ----------------
__global__ __launch_bounds__(256) void router_kernel(
    const float* __restrict__ x, const float* __restrict__ gw, const float* __restrict__ gb)
{
    __shared__ float4 sgw[E_ * D_ / 4];    // 32 KB gate matrix
    int tid = threadIdx.x;
    for (int i = tid; i < E_ * D_ / 4; i += 256) sgw[i] = ((const float4*)gw)[i];
    __syncthreads();

    int warp = tid >> 5, lane = tid & 31;
    int t = blockIdx.x * 8 + warp;
    const float4* xr = (const float4*)(x + (size_t)t * D_);

    float acc[E_];
    #pragma unroll
    for (int e = 0; e < E_; ++e) acc[e] = 0.f;

    #pragma unroll
    for (int i = 0; i < D_ / 128; ++i) {          // 8 float4 per lane
        float4 xv = xr[lane + 32 * i];
        #pragma unroll
        for (int e = 0; e < E_; ++e) {
            float4 g = sgw[e * (D_ / 4) + lane + 32 * i];
            acc[e] += xv.x * g.x + xv.y * g.y + xv.z * g.z + xv.w * g.w;
        }
    }
    #pragma unroll
    for (int e = 0; e < E_; ++e)
        #pragma unroll
        for (int o = 16; o; o >>= 1) acc[e] += __shfl_down_sync(0xffffffffu, acc[e], o);

    if (lane == 0) {
        float l[E_], m = -1e30f;
        #pragma unroll
        for (int e = 0; e < E_; ++e) { l[e] = acc[e] + gb[e]; m = fmaxf(m, l[e]); }
        float p[E_], s = 0.f;
        #pragma unroll
        for (int e = 0; e < E_; ++e) { p[e] = expf(l[e] - m); s += p[e]; }
        float inv = 1.f / s;
        int i0 = 0; float m0 = -1.f;
        #pragma unroll
        for (int e = 0; e < E_; ++e) {
            p[e] *= inv;
            g_probs[(size_t)t * E_ + e] = p[e];
            if (p[e] > m0) { m0 = p[e]; i0 = e; }
        }
        int i1 = -1; float m1 = -1.f;
        #pragma unroll
        for (int e = 0; e < E_; ++e)
            if (e != i0 && p[e] > m1) { m1 = p[e]; i1 = e; }
        float inv2 = 1.f / (m0 + m1 + 1e-9f);
        g_topk[t * 2 + 0] = i0;  g_topw[t * 2 + 0] = m0 * inv2;
        g_topk[t * 2 + 1] = i1;  g_topw[t * 2 + 1] = m1 * inv2;
        atomicAdd(&g_counts[i0], 1);
        atomicAdd(&g_counts[i1], 1);
    }
}

// ---------------- setup: offsets, tile map, scatter, pads (1 block) ----------------
__global__ void setup_kernel() {
    __shared__ int offs[E_], cnt[E_], padc[E_], cur[E_];
    int tid = threadIdx.x;
    if (tid == 0) {
        int acc = 0;
        for (int e = 0; e < E_; ++e) {
            cnt[e] = g_counts[e];
            offs[e] = acc;
            padc[e] = ((cnt[e] + 127) >> 7) << 7;
            acc += padc[e];
        }
        int tt = 0;
        for (int e = 0; e < E_; ++e)
            for (int j = 0; j < (padc[e] >> 7); ++j) g_tile_expert[tt++] = e;
        for (; tt < NTILES; ++tt) g_tile_expert[tt] = -1;
    }
    if (tid < E_) cur[tid] = 0;
    __syncthreads();

    for (int idx = tid; idx < B_ * 2; idx += blockDim.x) {
        int t = idx >> 1;
        int e = g_topk[idx];
        int pos = offs[e] + atomicAdd(&cur[e], 1);
        g_tok[pos] = t;
        g_wgt[pos] = g_topw[idx];
    }
    // pads (independent of scatter positions)
    for (int e = 0; e < E_; ++e)
        for (int j = cnt[e] + tid; j < padc[e]; j += blockDim.x) {
            g_tok[offs[e] + j] = 0;
            g_wgt[offs[e] + j] = 0.f;
        }
}

// ---------------- grouped TF32 GEMM (BM=BN=128, BK=16, 256 threads) ----------------
// FIRST:  g_h[row] = gelu(x[tok[row]] @ W1[e] + b1[e])         (KDIM=1024, NTOT=4096)
// !FIRST: out[tok[row]] += wgt[row] * (g_h[row] @ W2[e] + b2[e]) (KDIM=4096, NTOT=1024)
template<int KDIM, int NTOT, bool FIRST>
__global__ __launch_bounds__(256) void moe_gemm(
    const float* __restrict__ x,
    const float* __restrict__ W,
    const float* __restrict__ bias,
    float* __restrict__ out)
{
    int e = g_tile_expert[blockIdx.y];
    if (e < 0) return;
    const int row0 = blockIdx.y * 128;
    const int n0   = blockIdx.x * 128;
    const int tid  = threadIdx.x;

    __shared__ float As[2][128][20];   // 16 cols + pad 4
    __shared__ float Bs[2][16][136];   // 128 cols + pad 8 (conflict-free frag reads)
    __shared__ int   s_tok[128];
    __shared__ float s_wgt[128];

    if (tid < 128) { s_tok[tid] = g_tok[row0 + tid]; s_wgt[tid] = g_wgt[row0 + tid]; }
    __syncthreads();

    const float* We = W + (size_t)e * KDIM * NTOT;

    const int arow  = tid >> 1;            // 0..127
    const int acol0 = (tid & 1) * 8;       // 0 or 8
    const float* Arow;
    if (FIRST) Arow = x + (size_t)s_tok[arow] * KDIM;
    else       Arow = g_h + (size_t)(row0 + arow) * KDIM;

    const int bk0 = tid >> 5;              // 0..7  (and +8 for second op)
    const int bc  = (tid & 31) * 4;        // 0..124

    auto load_tile = [&](int kt, int buf) {
        int k0 = kt * 16;
        cp16(&As[buf][arow][acol0],     Arow + k0 + acol0);
        cp16(&As[buf][arow][acol0 + 4], Arow + k0 + acol0 + 4);
        const float* Bp = We + (size_t)k0 * NTOT + n0;
        cp16(&Bs[buf][bk0][bc],     Bp + (size_t)bk0 * NTOT + bc);
        cp16(&Bs[buf][bk0 + 8][bc], Bp + (size_t)(bk0 + 8) * NTOT + bc);
    };

    const int warp = tid >> 5, lane = tid & 31;
    const int wm = (warp & 3) * 32;   // 4 warps along M
    const int wn = (warp >> 2) * 64;  // 2 warps along N
    const int gid = lane >> 2, tig = lane & 3;

    float acc[2][8][4];
    #pragma unroll
    for (int mf = 0; mf < 2; ++mf)
        #pragma unroll
        for (int nf = 0; nf < 8; ++nf)
            #pragma unroll
            for (int i = 0; i < 4; ++i) acc[mf][nf][i] = 0.f;

    constexpr int KT = KDIM / 16;
    load_tile(0, 0);
    CP_COMMIT();

    for (int kt = 0; kt < KT; ++kt) {
        int cb = kt & 1;
        if (kt + 1 < KT) {
            load_tile(kt + 1, cb ^ 1);
            CP_COMMIT();
            asm volatile("cp.async.wait_group 1;\n");
        } else {
            asm volatile("cp.async.wait_group 0;\n");
        }
        __syncthreads();

        #pragma unroll
        for (int kk = 0; kk < 16; kk += 8) {
            uint32_t a[2][4], b[8][2];
            #pragma unroll
            for (int mf = 0; mf < 2; ++mf) {
                int r = wm + mf * 16 + gid;
                a[mf][0] = f2tf(As[cb][r    ][kk + tig]);
                a[mf][1] = f2tf(As[cb][r + 8][kk + tig]);
                a[mf][2] = f2tf(As[cb][r    ][kk + tig + 4]);
                a[mf][3] = f2tf(As[cb][r + 8][kk + tig + 4]);
            }
            #pragma unroll
            for (int nf = 0; nf < 8; ++nf) {
                int c = wn + nf * 8 + gid;
                b[nf][0] = f2tf(Bs[cb][kk + tig    ][c]);
                b[nf][1] = f2tf(Bs[cb][kk + tig + 4][c]);
            }
            #pragma unroll
            for (int mf = 0; mf < 2; ++mf)
                #pragma unroll
                for (int nf = 0; nf < 8; ++nf)
                    asm volatile(
                        "mma.sync.aligned.m16n8k8.row.col.f32.tf32.tf32.f32 "
                        "{%0,%1,%2,%3},{%4,%5,%6,%7},{%8,%9},{%0,%1,%2,%3};\n"
                        : "+f"(acc[mf][nf][0]), "+f"(acc[mf][nf][1]),
                          "+f"(acc[mf][nf][2]), "+f"(acc[mf][nf][3])
                        : "r"(a[mf][0]), "r"(a[mf][1]), "r"(a[mf][2]), "r"(a[mf][3]),
                          "r"(b[nf][0]), "r"(b[nf][1]));
        }
        __syncthreads();
    }

    // epilogue
    #pragma unroll
    for (int mf = 0; mf < 2; ++mf) {
        #pragma unroll
        for (int nf = 0; nf < 8; ++nf) {
            #pragma unroll
            for (int i = 0; i < 4; ++i) {
                int rl = wm + mf * 16 + gid + ((i >> 1) ? 8 : 0);
                int cl = wn + nf * 8 + tig * 2 + (i & 1);
                int gc = n0 + cl;
                float v = acc[mf][nf][i] + bias[e * NTOT + gc];
                if constexpr (FIRST) {
                    v = 0.5f * v * (1.f + erff(v * 0.70710678118654752f));  // exact GELU
                    g_h[(size_t)(row0 + rl) * NTOT + gc] = v;
                } else {
                    float w = s_wgt[rl];
                    int tok  = s_tok[rl];
                    atomicAdd(&out[(size_t)tok * O_ + gc], w * v);  // pads: w==0 -> +0.0f
                }
            }
        }
    }
}

// ---------------- aux loss: deterministic fixed-order reduction ----------------
__global__ void aux_kernel(float* __restrict__ out, int aux_idx) {
    __shared__ float sm[256 * E_];
    int tid = threadIdx.x;
    float ps[E_];
    #pragma unroll
    for (int e = 0; e < E_; ++e) ps[e] = 0.f;
    for (int t = tid; t < B_; t += 256)
        #pragma unroll
        for (int e = 0; e < E_; ++e) ps[e] += g_probs[(size_t)t * E_ + e];
    #pragma unroll
    for (int e = 0; e < E_; ++e) sm[tid * E_ + e] = ps[e];
    __syncthreads();
    for (int o = 128; o; o >>= 1) {
        if (tid < o)
            #pragma unroll
            for (int e = 0; e < E_; ++e) sm[tid * E_ + e] += sm[(tid + o) * E_ + e];
        __syncthreads();
    }
    if (tid == 0) {
        float aux = 0.f;
        #pragma unroll
        for (int e = 0; e < E_; ++e) {
            float f = (float)g_counts[e] * (1.f / B_);
            float p = sm[e] * (1.f / B_);
            aux += f * p;
        }
        out[aux_idx] = aux * (0.01f * E_);
    }
}

// ---------------- launch ----------------
extern "C" void kernel_launch(void* const* d_in, const int* in_sizes, int n_in,
                              void* d_out, int out_size)
{
    const float* x  = (const float*)d_in[0];
    const float* w1 = (const float*)d_in[1];
    const float* b1 = (const float*)d_in[2];
    const float* w2 = (const float*)d_in[3];
    const float* b2 = (const float*)d_in[4];
    const float* gw = (const float*)d_in[5];
    const float* gb = (const float*)d_in[6];
    float* out = (float*)d_out;

    init_kernel<<<(B_ * O_) / 1024, 256>>>(out);       // zero output + counters
    router_kernel<<<B_ / 8, 256>>>(x, gw, gb);
    setup_kernel<<<1, 256>>>();
    moe_gemm<D_, H_, true ><<<dim3(H_ / 128, NTILES), 256>>>(x, w1, b1, out);
    moe_gemm<H_, O_, false><<<dim3(O_ / 128, NTILES), 256>>>(x, w2, b2, out);
    aux_kernel<<<1, 256>>>(out, out_size - 1);
}

// round 5
// speedup vs baseline: 1.1241x; 1.1241x over previous
#include <cuda_runtime.h>
#include <cstdint>

#define E_ 8
#define D_ 1024
#define H_ 4096
#define O_ 1024
#define B_ 4096
#define MAXROWS 9216          // 8192 rows + per-expert padding to 128, <= 72 tiles
#define NTILES  72            // MAXROWS / 128

// ---------------- static device scratch (no allocations allowed) ----------------
__device__ float g_h  [(size_t)MAXROWS * H_];   // gelu(x@W1+b1), tf32-rounded
__device__ float g_xa [(size_t)MAXROWS * D_];   // gathered + tf32-rounded x rows
__device__ float g_wr [(size_t)E_ * D_ * H_];   // rounded weights (w1, then reused for w2)
__device__ int   g_tok[MAXROWS];
__device__ float g_wgt[MAXROWS];
__device__ int   g_counts[E_];
__device__ int   g_tile_expert[NTILES];
__device__ float g_probs[(size_t)B_ * E_];
__device__ int   g_topk[B_ * 2];
__device__ float g_topw[B_ * 2];

// ---------------- helpers ----------------
__device__ __forceinline__ uint32_t f2tf(float f) {
    uint32_t u;
    asm("cvt.rna.tf32.f32 %0, %1;" : "=r"(u) : "f"(f));
    return u;
}
__device__ __forceinline__ float rna32(float f) { return __uint_as_float(f2tf(f)); }

__device__ __forceinline__ void cp16(void* s, const void* g) {
    uint32_t sa = (uint32_t)__cvta_generic_to_shared(s);
    asm volatile("cp.async.cg.shared.global [%0], [%1], 16;\n" :: "r"(sa), "l"(g));
}
#define CP_COMMIT() asm volatile("cp.async.commit_group;\n")

// ---------------- init: zero output + counters ----------------
__global__ void init_kernel(float* __restrict__ out) {
    size_t i = (size_t)blockIdx.x * blockDim.x + threadIdx.x;   // B_*O_/4 float4s
    ((float4*)out)[i] = make_float4(0.f, 0.f, 0.f, 0.f);
    if (blockIdx.x == 0 && threadIdx.x < E_) g_counts[threadIdx.x] = 0;
}

// ---------------- pre-round weights to tf32 (removes cvt from GEMM loop) ----------
__global__ __launch_bounds__(256) void round_kernel(
    const float* __restrict__ src, float* __restrict__ dst)
{
    size_t i = (size_t)blockIdx.x * blockDim.x + threadIdx.x;   // one float4 each
    float4 v = ((const float4*)src)[i];
    v.x = rna32(v.x); v.y = rna32(v.y); v.z = rna32(v.z); v.w = rna32(v.w);
    ((float4*)dst)[i] = v;
}

// ---------------- router: 1 warp per token (proven R1) ----------------
__global__ __launch_bounds__(256) void router_kernel(
    const float* __restrict__ x, const float* __restrict__ gw, const float* __restrict__ gb)
{
    __shared__ float4 sgw[E_ * D_ / 4];    // 32 KB gate matrix
    int tid = threadIdx.x;
    for (int i = tid; i < E_ * D_ / 4; i += 256) sgw[i] = ((const float4*)gw)[i];
    __syncthreads();

    int warp = tid >> 5, lane = tid & 31;
    int t = blockIdx.x * 8 + warp;
    const float4* xr = (const float4*)(x + (size_t)t * D_);

    float acc[E_];
    #pragma unroll
    for (int e = 0; e < E_; ++e) acc[e] = 0.f;

    #pragma unroll
    for (int i = 0; i < D_ / 128; ++i) {          // 8 float4 per lane
        float4 xv = xr[lane + 32 * i];
        #pragma unroll
        for (int e = 0; e < E_; ++e) {
            float4 g = sgw[e * (D_ / 4) + lane + 32 * i];
            acc[e] += xv.x * g.x + xv.y * g.y + xv.z * g.z + xv.w * g.w;
        }
    }
    #pragma unroll
    for (int e = 0; e < E_; ++e)
        #pragma unroll
        for (int o = 16; o; o >>= 1) acc[e] += __shfl_down_sync(0xffffffffu, acc[e], o);

    if (lane == 0) {
        float l[E_], m = -1e30f;
        #pragma unroll
        for (int e = 0; e < E_; ++e) { l[e] = acc[e] + gb[e]; m = fmaxf(m, l[e]); }
        float p[E_], s = 0.f;
        #pragma unroll
        for (int e = 0; e < E_; ++e) { p[e] = expf(l[e] - m); s += p[e]; }
        float inv = 1.f / s;
        int i0 = 0; float m0 = -1.f;
        #pragma unroll
        for (int e = 0; e < E_; ++e) {
            p[e] *= inv;
            g_probs[(size_t)t * E_ + e] = p[e];
            if (p[e] > m0) { m0 = p[e]; i0 = e; }
        }
        int i1 = -1; float m1 = -1.f;
        #pragma unroll
        for (int e = 0; e < E_; ++e)
            if (e != i0 && p[e] > m1) { m1 = p[e]; i1 = e; }
        float inv2 = 1.f / (m0 + m1 + 1e-9f);
        g_topk[t * 2 + 0] = i0;  g_topw[t * 2 + 0] = m0 * inv2;
        g_topk[t * 2 + 1] = i1;  g_topw[t * 2 + 1] = m1 * inv2;
        atomicAdd(&g_counts[i0], 1);
        atomicAdd(&g_counts[i1], 1);
    }
}

// ---------------- setup: offsets, tile map, scatter, pads (proven R1) -----------
__global__ void setup_kernel() {
    __shared__ int offs[E_], cnt[E_], padc[E_], cur[E_];
    int tid = threadIdx.x;
    if (tid == 0) {
        int acc = 0;
        for (int e = 0; e < E_; ++e) {
            cnt[e] = g_counts[e];
            offs[e] = acc;
            padc[e] = ((cnt[e] + 127) >> 7) << 7;
            acc += padc[e];
        }
        int tt = 0;
        for (int e = 0; e < E_; ++e)
            for (int j = 0; j < (padc[e] >> 7); ++j) g_tile_expert[tt++] = e;
        for (; tt < NTILES; ++tt) g_tile_expert[tt] = -1;
    }
    if (tid < E_) cur[tid] = 0;
    __syncthreads();

    for (int idx = tid; idx < B_ * 2; idx += blockDim.x) {
        int t = idx >> 1;
        int e = g_topk[idx];
        int pos = offs[e] + atomicAdd(&cur[e], 1);
        g_tok[pos] = t;
        g_wgt[pos] = g_topw[idx];
    }
    for (int e = 0; e < E_; ++e)
        for (int j = cnt[e] + tid; j < padc[e]; j += blockDim.x) {
            g_tok[offs[e] + j] = 0;
            g_wgt[offs[e] + j] = 0.f;
        }
}

// ---------------- gather + tf32-round x rows into g_xa ----------------
__global__ __launch_bounds__(256) void gather_kernel(const float* __restrict__ x) {
    int tile = blockIdx.x;
    if (g_tile_expert[tile] < 0) return;
    int r0 = tile * 128 + blockIdx.y * 16;    // 16 rows per block
    for (int r = r0; r < r0 + 16; ++r) {
        const float4* src = (const float4*)(x + (size_t)g_tok[r] * D_);
        float4* dst = (float4*)(g_xa + (size_t)r * D_);
        int j = threadIdx.x;                   // D_/4 = 256 float4 per row
        float4 v = src[j];
        v.x = rna32(v.x); v.y = rna32(v.y); v.z = rna32(v.z); v.w = rna32(v.w);
        dst[j] = v;
    }
}

// ---------------- grouped TF32 GEMM (BM=BN=128, BK=16, 256 threads) ----------------
// All operands pre-rounded to tf32 -> ZERO cvt in the inner loop.
// FIRST:  g_h[row] = rna(gelu(A[row] @ W1r[e] + b1[e]))
// !FIRST: out[tok[row]] += wgt[row] * (A[row] @ W2r[e] + b2[e])
template<int KDIM, int NTOT, bool FIRST>
__global__ __launch_bounds__(256, 2) void moe_gemm(
    const float* __restrict__ A,      // contiguous rows [tile*128 + r][KDIM], tf32-exact
    const float* __restrict__ W,      // [E][KDIM][NTOT], tf32-exact
    const float* __restrict__ bias,
    float* __restrict__ out)
{
    int e = g_tile_expert[blockIdx.y];
    if (e < 0) return;
    const int row0 = blockIdx.y * 128;
    const int n0   = blockIdx.x * 128;
    const int tid  = threadIdx.x;

    __shared__ float As[2][128][20];   // 16 cols + pad 4
    __shared__ float Bs[2][16][136];   // 128 cols + pad 8
    __shared__ int   s_tok[128];
    __shared__ float s_wgt[128];

    if (!FIRST && tid < 128) { s_tok[tid] = g_tok[row0 + tid]; s_wgt[tid] = g_wgt[row0 + tid]; }

    const float* We = W + (size_t)e * KDIM * NTOT;

    const int arow  = tid >> 1;            // 0..127
    const int acol0 = (tid & 1) * 8;       // 0 or 8
    const float* Arow = A + (size_t)(row0 + arow) * KDIM;

    const int bk0 = tid >> 5;              // 0..7 (and +8)
    const int bc  = (tid & 31) * 4;        // 0..124

    auto load_tile = [&](int kt, int buf) {
        int k0 = kt * 16;
        cp16(&As[buf][arow][acol0],     Arow + k0 + acol0);
        cp16(&As[buf][arow][acol0 + 4], Arow + k0 + acol0 + 4);
        const float* Bp = We + (size_t)k0 * NTOT + n0;
        cp16(&Bs[buf][bk0][bc],     Bp + (size_t)bk0 * NTOT + bc);
        cp16(&Bs[buf][bk0 + 8][bc], Bp + (size_t)(bk0 + 8) * NTOT + bc);
    };

    const int warp = tid >> 5, lane = tid & 31;
    const int wm = (warp & 3) * 32;   // 4 warps along M
    const int wn = (warp >> 2) * 64;  // 2 warps along N
    const int gid = lane >> 2, tig = lane & 3;

    float acc[2][8][4];
    #pragma unroll
    for (int mf = 0; mf < 2; ++mf)
        #pragma unroll
        for (int nf = 0; nf < 8; ++nf)
            #pragma unroll
            for (int i = 0; i < 4; ++i) acc[mf][nf][i] = 0.f;

    constexpr int KT = KDIM / 16;
    load_tile(0, 0);
    CP_COMMIT();

    for (int kt = 0; kt < KT; ++kt) {
        int cb = kt & 1;
        if (kt + 1 < KT) {
            load_tile(kt + 1, cb ^ 1);
            CP_COMMIT();
            asm volatile("cp.async.wait_group 1;\n");
        } else {
            asm volatile("cp.async.wait_group 0;\n");
        }
        __syncthreads();

        #pragma unroll
        for (int kk = 0; kk < 16; kk += 8) {
            uint32_t a[2][4], b[8][2];
            #pragma unroll
            for (int mf = 0; mf < 2; ++mf) {
                int r = wm + mf * 16 + gid;
                a[mf][0] = __float_as_uint(As[cb][r    ][kk + tig]);
                a[mf][1] = __float_as_uint(As[cb][r + 8][kk + tig]);
                a[mf][2] = __float_as_uint(As[cb][r    ][kk + tig + 4]);
                a[mf][3] = __float_as_uint(As[cb][r + 8][kk + tig + 4]);
            }
            #pragma unroll
            for (int nf = 0; nf < 8; ++nf) {
                int c = wn + nf * 8 + gid;
                b[nf][0] = __float_as_uint(Bs[cb][kk + tig    ][c]);
                b[nf][1] = __float_as_uint(Bs[cb][kk + tig + 4][c]);
            }
            #pragma unroll
            for (int mf = 0; mf < 2; ++mf)
                #pragma unroll
                for (int nf = 0; nf < 8; ++nf)
                    asm volatile(
                        "mma.sync.aligned.m16n8k8.row.col.f32.tf32.tf32.f32 "
                        "{%0,%1,%2,%3},{%4,%5,%6,%7},{%8,%9},{%0,%1,%2,%3};\n"
                        : "+f"(acc[mf][nf][0]), "+f"(acc[mf][nf][1]),
                          "+f"(acc[mf][nf][2]), "+f"(acc[mf][nf][3])
                        : "r"(a[mf][0]), "r"(a[mf][1]), "r"(a[mf][2]), "r"(a[mf][3]),
                          "r"(b[nf][0]), "r"(b[nf][1]));
        }
        __syncthreads();
    }

    // epilogue
    #pragma unroll
    for (int mf = 0; mf < 2; ++mf) {
        #pragma unroll
        for (int nf = 0; nf < 8; ++nf) {
            #pragma unroll
            for (int i = 0; i < 4; ++i) {
                int rl = wm + mf * 16 + gid + ((i >> 1) ? 8 : 0);
                int cl = wn + nf * 8 + tig * 2 + (i & 1);
                int gc = n0 + cl;
                float v = acc[mf][nf][i] + bias[e * NTOT + gc];
                if constexpr (FIRST) {
                    v = 0.5f * v * (1.f + erff(v * 0.70710678118654752f));  // exact GELU
                    g_h[(size_t)(row0 + rl) * NTOT + gc] = rna32(v);
                } else {
                    float w = s_wgt[rl];
                    int tok  = s_tok[rl];
                    atomicAdd(&out[(size_t)tok * O_ + gc], w * v);  // pads: w==0 -> +0.0f
                }
            }
        }
    }
}

// ---------------- aux loss: deterministic fixed-order reduction (proven R1) -----
__global__ void aux_kernel(float* __restrict__ out, int aux_idx) {
    __shared__ float sm[256 * E_];
    int tid = threadIdx.x;
    float ps[E_];
    #pragma unroll
    for (int e = 0; e < E_; ++e) ps[e] = 0.f;
    for (int t = tid; t < B_; t += 256)
        #pragma unroll
        for (int e = 0; e < E_; ++e) ps[e] += g_probs[(size_t)t * E_ + e];
    #pragma unroll
    for (int e = 0; e < E_; ++e) sm[tid * E_ + e] = ps[e];
    __syncthreads();
    for (int o = 128; o; o >>= 1) {
        if (tid < o)
            #pragma unroll
            for (int e = 0; e < E_; ++e) sm[tid * E_ + e] += sm[(tid + o) * E_ + e];
        __syncthreads();
    }
    if (tid == 0) {
        float aux = 0.f;
        #pragma unroll
        for (int e = 0; e < E_; ++e) {
            float f = (float)g_counts[e] * (1.f / B_);
            float p = sm[e] * (1.f / B_);
            aux += f * p;
        }
        out[aux_idx] = aux * (0.01f * E_);
    }
}

// ---------------- launch ----------------
extern "C" void kernel_launch(void* const* d_in, const int* in_sizes, int n_in,
                              void* d_out, int out_size)
{
    const float* x  = (const float*)d_in[0];
    const float* w1 = (const float*)d_in[1];
    const float* b1 = (const float*)d_in[2];
    const float* w2 = (const float*)d_in[3];
    const float* b2 = (const float*)d_in[4];
    const float* gw = (const float*)d_in[5];
    const float* gb = (const float*)d_in[6];
    float* out = (float*)d_out;

    float* p_xa; cudaGetSymbolAddress((void**)&p_xa, g_xa);
    float* p_h;  cudaGetSymbolAddress((void**)&p_h,  g_h);
    float* p_wr; cudaGetSymbolAddress((void**)&p_wr, g_wr);

    init_kernel<<<(B_ * O_) / 1024, 256>>>(out);
    router_kernel<<<B_ / 8, 256>>>(x, gw, gb);
    setup_kernel<<<1, 256>>>();
    gather_kernel<<<dim3(NTILES, 8), 256>>>(x);

    // g_wr is reused: w1 for GEMM1, then w2 for GEMM2 (launches are serial)
    round_kernel<<<(E_ * D_ * H_) / 1024, 256>>>(w1, p_wr);
    moe_gemm<D_, H_, true ><<<dim3(H_ / 128, NTILES), 256>>>(p_xa, p_wr, b1, out);
    round_kernel<<<(E_ * H_ * O_) / 1024, 256>>>(w2, p_wr);
    moe_gemm<H_, O_, false><<<dim3(O_ / 128, NTILES), 256>>>(p_h, p_wr, b2, out);

    aux_kernel<<<1, 256>>>(out, out_size - 1);
}

// round 6
// speedup vs baseline: 1.8863x; 1.6780x over previous
#include <cuda_runtime.h>
#include <cuda_fp16.h>
#include <cstdint>

#define E_ 8
#define D_ 1024
#define H_ 4096
#define O_ 1024
#define B_ 4096
#define MAXROWS 9216          // 8192 rows + per-expert padding to 128, <= 72 tiles
#define NTILES  72            // MAXROWS / 128

// ---------------- static device scratch (no allocations allowed) ----------------
__device__ __half g_h [(size_t)MAXROWS * H_];   // gelu(x@W1+b1), half
__device__ __half g_xa[(size_t)MAXROWS * D_];   // gathered x rows, half
__device__ __half g_wt[(size_t)E_ * D_ * H_];   // transposed weights [e][n][k] half (reused)
__device__ int    g_tok[MAXROWS];
__device__ float  g_wgt[MAXROWS];
__device__ int    g_counts[E_];
__device__ int    g_tile_expert[NTILES];
__device__ float  g_probs[(size_t)B_ * E_];
__device__ int    g_topk[B_ * 2];
__device__ float  g_topw[B_ * 2];

// ---------------- helpers ----------------
__device__ __forceinline__ void cp16(void* s, const void* g) {
    uint32_t sa = (uint32_t)__cvta_generic_to_shared(s);
    asm volatile("cp.async.cg.shared.global [%0], [%1], 16;\n" :: "r"(sa), "l"(g));
}
#define CP_COMMIT() asm volatile("cp.async.commit_group;\n")

__device__ __forceinline__ uint32_t smem_u32(const void* p) {
    return (uint32_t)__cvta_generic_to_shared(p);
}

// ---------------- init: zero output + counters ----------------
__global__ void init_kernel(float* __restrict__ out) {
    size_t i = (size_t)blockIdx.x * blockDim.x + threadIdx.x;   // B_*O_/4 float4s
    ((float4*)out)[i] = make_float4(0.f, 0.f, 0.f, 0.f);
    if (blockIdx.x == 0 && threadIdx.x < E_) g_counts[threadIdx.x] = 0;
}

// ---------------- transpose + f32->half: in [e][KD][ND] -> out [e][ND][KD] ------
template<int KD, int ND>
__global__ __launch_bounds__(256) void transpose_half_kernel(
    const float* __restrict__ in, __half* __restrict__ out)
{
    __shared__ float sm[32][33];
    int e = blockIdx.z;
    int n0 = blockIdx.x * 32, k0 = blockIdx.y * 32;
    int tx = threadIdx.x & 31, ty = threadIdx.x >> 5;   // 32 x 8
    const float* ine = in + (size_t)e * KD * ND;
    #pragma unroll
    for (int i = 0; i < 4; ++i)
        sm[ty + i * 8][tx] = ine[(size_t)(k0 + ty + i * 8) * ND + n0 + tx];
    __syncthreads();
    __half2* oute = (__half2*)(out + (size_t)e * ND * KD);
    int wk2 = threadIdx.x & 15;          // half2 index along k
    int wn  = threadIdx.x >> 4;          // 0..15
    #pragma unroll
    for (int i = 0; i < 2; ++i) {
        int n = wn + i * 16;
        oute[(size_t)(n0 + n) * (KD / 2) + (k0 >> 1) + wk2] =
            __floats2half2_rn(sm[wk2 * 2][n], sm[wk2 * 2 + 1][n]);
    }
}

// ---------------- router: 1 warp per token (proven R1) ----------------
__global__ __launch_bounds__(256) void router_kernel(
    const float* __restrict__ x, const float* __restrict__ gw, const float* __restrict__ gb)
{
    __shared__ float4 sgw[E_ * D_ / 4];    // 32 KB gate matrix
    int tid = threadIdx.x;
    for (int i = tid; i < E_ * D_ / 4; i += 256) sgw[i] = ((const float4*)gw)[i];
    __syncthreads();

    int warp = tid >> 5, lane = tid & 31;
    int t = blockIdx.x * 8 + warp;
    const float4* xr = (const float4*)(x + (size_t)t * D_);

    float acc[E_];
    #pragma unroll
    for (int e = 0; e < E_; ++e) acc[e] = 0.f;

    #pragma unroll
    for (int i = 0; i < D_ / 128; ++i) {
        float4 xv = xr[lane + 32 * i];
        #pragma unroll
        for (int e = 0; e < E_; ++e) {
            float4 g = sgw[e * (D_ / 4) + lane + 32 * i];
            acc[e] += xv.x * g.x + xv.y * g.y + xv.z * g.z + xv.w * g.w;
        }
    }
    #pragma unroll
    for (int e = 0; e < E_; ++e)
        #pragma unroll
        for (int o = 16; o; o >>= 1) acc[e] += __shfl_down_sync(0xffffffffu, acc[e], o);

    if (lane == 0) {
        float l[E_], m = -1e30f;
        #pragma unroll
        for (int e = 0; e < E_; ++e) { l[e] = acc[e] + gb[e]; m = fmaxf(m, l[e]); }
        float p[E_], s = 0.f;
        #pragma unroll
        for (int e = 0; e < E_; ++e) { p[e] = expf(l[e] - m); s += p[e]; }
        float inv = 1.f / s;
        int i0 = 0; float m0 = -1.f;
        #pragma unroll
        for (int e = 0; e < E_; ++e) {
            p[e] *= inv;
            g_probs[(size_t)t * E_ + e] = p[e];
            if (p[e] > m0) { m0 = p[e]; i0 = e; }
        }
        int i1 = -1; float m1 = -1.f;
        #pragma unroll
        for (int e = 0; e < E_; ++e)
            if (e != i0 && p[e] > m1) { m1 = p[e]; i1 = e; }
        float inv2 = 1.f / (m0 + m1 + 1e-9f);
        g_topk[t * 2 + 0] = i0;  g_topw[t * 2 + 0] = m0 * inv2;
        g_topk[t * 2 + 1] = i1;  g_topw[t * 2 + 1] = m1 * inv2;
        atomicAdd(&g_counts[i0], 1);
        atomicAdd(&g_counts[i1], 1);
    }
}

// ---------------- setup: offsets, tile map, scatter, pads (proven R1) -----------
__global__ void setup_kernel() {
    __shared__ int offs[E_], cnt[E_], padc[E_], cur[E_];
    int tid = threadIdx.x;
    if (tid == 0) {
        int acc = 0;
        for (int e = 0; e < E_; ++e) {
            cnt[e] = g_counts[e];
            offs[e] = acc;
            padc[e] = ((cnt[e] + 127) >> 7) << 7;
            acc += padc[e];
        }
        int tt = 0;
        for (int e = 0; e < E_; ++e)
            for (int j = 0; j < (padc[e] >> 7); ++j) g_tile_expert[tt++] = e;
        for (; tt < NTILES; ++tt) g_tile_expert[tt] = -1;
    }
    if (tid < E_) cur[tid] = 0;
    __syncthreads();

    for (int idx = tid; idx < B_ * 2; idx += blockDim.x) {
        int t = idx >> 1;
        int e = g_topk[idx];
        int pos = offs[e] + atomicAdd(&cur[e], 1);
        g_tok[pos] = t;
        g_wgt[pos] = g_topw[idx];
    }
    for (int e = 0; e < E_; ++e)
        for (int j = cnt[e] + tid; j < padc[e]; j += blockDim.x) {
            g_tok[offs[e] + j] = 0;
            g_wgt[offs[e] + j] = 0.f;
        }
}

// ---------------- gather x rows -> half into g_xa ----------------
__global__ __launch_bounds__(256) void gather_kernel(const float* __restrict__ x) {
    int tile = blockIdx.x;
    if (g_tile_expert[tile] < 0) return;
    int r0 = tile * 128 + blockIdx.y * 16;    // 16 rows per block
    for (int r = r0; r < r0 + 16; ++r) {
        const float4* src = (const float4*)(x + (size_t)g_tok[r] * D_);
        __half2* dst = (__half2*)(g_xa + (size_t)r * D_);
        int j = threadIdx.x;                   // D_/4 = 256 float4 per row
        float4 v = src[j];
        dst[j * 2 + 0] = __floats2half2_rn(v.x, v.y);
        dst[j * 2 + 1] = __floats2half2_rn(v.z, v.w);
    }
}

// ---------------- grouped FP16 GEMM (BM=BN=128, BK=32, 256 threads) ----------------
// A: [row][k] half (k-contiguous).  W: [e][n][k] half (k-contiguous).
// SMEM rows: 32 data halves + 8 pad = 20 uint32 per row (conflict-free).
// A-fragments via ldmatrix.x4; B-fragments via LDS.32 (consecutive-k half2).
// FIRST:  g_h[row] = half(gelu(A@W1 + b1))
// !FIRST: out[tok[row]] += wgt[row] * (A@W2 + b2)   (atomicAdd; pads have wgt==0)
template<int KDIM, int NTOT, bool FIRST>
__global__ __launch_bounds__(256, 2) void moe_gemm_h(
    const __half* __restrict__ A,
    const __half* __restrict__ W,
    const float* __restrict__ bias,
    float* __restrict__ out)
{
    int e = g_tile_expert[blockIdx.y];
    if (e < 0) return;
    const int row0 = blockIdx.y * 128;
    const int n0   = blockIdx.x * 128;
    const int tid  = threadIdx.x;

    __shared__ uint32_t As[2][128][20];   // 10240 B per buffer
    __shared__ uint32_t Bs[2][128][20];
    __shared__ int   s_tok[128];
    __shared__ float s_wgt[128];

    if (!FIRST && tid < 128) { s_tok[tid] = g_tok[row0 + tid]; s_wgt[tid] = g_wgt[row0 + tid]; }

    const __half* We = W + (size_t)e * NTOT * KDIM;   // [n][k]

    auto load_tile = [&](int kt, int buf) {
        const int kof = kt * 32;
        #pragma unroll
        for (int j = 0; j < 4; ++j) {
            int id = tid + j * 256;                 // 0..1023
            if (id < 512) {                         // A: 128 rows x 4 chunks(16B)
                int r = id >> 2, g = id & 3;
                cp16(&As[buf][r][g * 4], A + (size_t)(row0 + r) * KDIM + kof + g * 8);
            } else {                                // B: 128 n-rows x 4 chunks
                int id2 = id - 512;
                int r = id2 >> 2, g = id2 & 3;
                cp16(&Bs[buf][r][g * 4], We + (size_t)(n0 + r) * KDIM + kof + g * 8);
            }
        }
    };

    const int warp = tid >> 5, lane = tid & 31;
    const int wm = (warp & 3) * 32;   // 4 warps along M
    const int wn = (warp >> 2) * 64;  // 2 warps along N
    const int gid = lane >> 2, tig = lane & 3;

    // ldmatrix.x4 lane address for A: lanes 0-15 -> rows, cols kk; 16-31 -> rows, cols kk+8
    const int lrow = lane & 15, lhi = lane >> 4;
    const uint32_t as_s = smem_u32(&As[0][0][0]);
    // byte offset: row*(20*4) + lhi*8 halves(=16B); +mf*16 rows; +cb*10240; +kk*2 bytes
    const uint32_t a_lane = as_s + (uint32_t)(wm + lrow) * 80u + (uint32_t)lhi * 16u;

    float acc[2][8][4];
    #pragma unroll
    for (int mf = 0; mf < 2; ++mf)
        #pragma unroll
        for (int nf = 0; nf < 8; ++nf)
            #pragma unroll
            for (int i = 0; i < 4; ++i) acc[mf][nf][i] = 0.f;

    constexpr int KT = KDIM / 32;
    load_tile(0, 0);
    CP_COMMIT();

    for (int kt = 0; kt < KT; ++kt) {
        int cb = kt & 1;
        if (kt + 1 < KT) {
            load_tile(kt + 1, cb ^ 1);
            CP_COMMIT();
            asm volatile("cp.async.wait_group 1;\n");
        } else {
            asm volatile("cp.async.wait_group 0;\n");
        }
        __syncthreads();

        #pragma unroll
        for (int kk = 0; kk < 32; kk += 16) {
            const int kk2 = kk >> 1;                      // half2 column index
            uint32_t a[2][4], b[8][2];
            #pragma unroll
            for (int mf = 0; mf < 2; ++mf) {
                uint32_t addr = a_lane + (uint32_t)cb * 10240u
                              + (uint32_t)mf * 1280u + (uint32_t)kk * 2u;
                asm volatile(
                    "ldmatrix.sync.aligned.m8n8.x4.shared.b16 {%0,%1,%2,%3}, [%4];"
                    : "=r"(a[mf][0]), "=r"(a[mf][1]), "=r"(a[mf][2]), "=r"(a[mf][3])
                    : "r"(addr));
            }
            #pragma unroll
            for (int nf = 0; nf < 8; ++nf) {
                int c = wn + nf * 8 + gid;
                b[nf][0] = Bs[cb][c][kk2 + tig];
                b[nf][1] = Bs[cb][c][kk2 + tig + 4];
            }
            #pragma unroll
            for (int mf = 0; mf < 2; ++mf)
                #pragma unroll
                for (int nf = 0; nf < 8; ++nf)
                    asm volatile(
                        "mma.sync.aligned.m16n8k16.row.col.f32.f16.f16.f32 "
                        "{%0,%1,%2,%3},{%4,%5,%6,%7},{%8,%9},{%0,%1,%2,%3};\n"
                        : "+f"(acc[mf][nf][0]), "+f"(acc[mf][nf][1]),
                          "+f"(acc[mf][nf][2]), "+f"(acc[mf][nf][3])
                        : "r"(a[mf][0]), "r"(a[mf][1]), "r"(a[mf][2]), "r"(a[mf][3]),
                          "r"(b[nf][0]), "r"(b[nf][1]));
        }
        __syncthreads();
    }

    // -------- epilogue (c0,c1: row gid, cols tig*2+{0,1}; c2,c3: row gid+8) --------
    #pragma unroll
    for (int mf = 0; mf < 2; ++mf) {
        int rl = wm + mf * 16 + gid;
        #pragma unroll
        for (int nf = 0; nf < 8; ++nf) {
            int gc = n0 + wn + nf * 8 + tig * 2;
            float v00 = acc[mf][nf][0] + bias[e * NTOT + gc];
            float v01 = acc[mf][nf][1] + bias[e * NTOT + gc + 1];
            float v10 = acc[mf][nf][2] + bias[e * NTOT + gc];
            float v11 = acc[mf][nf][3] + bias[e * NTOT + gc + 1];
            if constexpr (FIRST) {
                v00 = 0.5f * v00 * (1.f + erff(v00 * 0.70710678118654752f));
                v01 = 0.5f * v01 * (1.f + erff(v01 * 0.70710678118654752f));
                v10 = 0.5f * v10 * (1.f + erff(v10 * 0.70710678118654752f));
                v11 = 0.5f * v11 * (1.f + erff(v11 * 0.70710678118654752f));
                *(__half2*)&g_h[(size_t)(row0 + rl)     * H_ + gc] = __floats2half2_rn(v00, v01);
                *(__half2*)&g_h[(size_t)(row0 + rl + 8) * H_ + gc] = __floats2half2_rn(v10, v11);
            } else {
                float w0 = s_wgt[rl];     int t0 = s_tok[rl];
                float w8 = s_wgt[rl + 8]; int t8 = s_tok[rl + 8];
                atomicAdd(&out[(size_t)t0 * O_ + gc    ], w0 * v00);
                atomicAdd(&out[(size_t)t0 * O_ + gc + 1], w0 * v01);
                atomicAdd(&out[(size_t)t8 * O_ + gc    ], w8 * v10);
                atomicAdd(&out[(size_t)t8 * O_ + gc + 1], w8 * v11);
            }
        }
    }
}

// ---------------- aux loss: deterministic fixed-order reduction (proven R1) -----
__global__ void aux_kernel(float* __restrict__ out, int aux_idx) {
    __shared__ float sm[256 * E_];
    int tid = threadIdx.x;
    float ps[E_];
    #pragma unroll
    for (int e = 0; e < E_; ++e) ps[e] = 0.f;
    for (int t = tid; t < B_; t += 256)
        #pragma unroll
        for (int e = 0; e < E_; ++e) ps[e] += g_probs[(size_t)t * E_ + e];
    #pragma unroll
    for (int e = 0; e < E_; ++e) sm[tid * E_ + e] = ps[e];
    __syncthreads();
    for (int o = 128; o; o >>= 1) {
        if (tid < o)
            #pragma unroll
            for (int e = 0; e < E_; ++e) sm[tid * E_ + e] += sm[(tid + o) * E_ + e];
        __syncthreads();
    }
    if (tid == 0) {
        float aux = 0.f;
        #pragma unroll
        for (int e = 0; e < E_; ++e) {
            float f = (float)g_counts[e] * (1.f / B_);
            float p = sm[e] * (1.f / B_);
            aux += f * p;
        }
        out[aux_idx] = aux * (0.01f * E_);
    }
}

// ---------------- launch ----------------
extern "C" void kernel_launch(void* const* d_in, const int* in_sizes, int n_in,
                              void* d_out, int out_size)
{
    const float* x  = (const float*)d_in[0];
    const float* w1 = (const float*)d_in[1];
    const float* b1 = (const float*)d_in[2];
    const float* w2 = (const float*)d_in[3];
    const float* b2 = (const float*)d_in[4];
    const float* gw = (const float*)d_in[5];
    const float* gb = (const float*)d_in[6];
    float* out = (float*)d_out;

    __half* p_xa; cudaGetSymbolAddress((void**)&p_xa, g_xa);
    __half* p_h;  cudaGetSymbolAddress((void**)&p_h,  g_h);
    __half* p_wt; cudaGetSymbolAddress((void**)&p_wt, g_wt);

    init_kernel<<<(B_ * O_) / 1024, 256>>>(out);
    router_kernel<<<B_ / 8, 256>>>(x, gw, gb);
    setup_kernel<<<1, 256>>>();
    gather_kernel<<<dim3(NTILES, 8), 256>>>(x);

    // g_wt reused: w1^T for GEMM1, then w2^T for GEMM2 (launches serial on one stream)
    transpose_half_kernel<D_, H_><<<dim3(H_ / 32, D_ / 32, E_), 256>>>(w1, p_wt);
    moe_gemm_h<D_, H_, true ><<<dim3(H_ / 128, NTILES), 256>>>(p_xa, p_wt, b1, out);
    transpose_half_kernel<H_, O_><<<dim3(O_ / 32, H_ / 32, E_), 256>>>(w2, p_wt);
    moe_gemm_h<H_, O_, false><<<dim3(O_ / 128, NTILES), 256>>>(p_h, p_wt, b2, out);

    aux_kernel<<<1, 256>>>(out, out_size - 1);
}

// round 7
// speedup vs baseline: 1.9927x; 1.0564x over previous
#include <cuda_runtime.h>
#include <cuda_fp16.h>
#include <cstdint>

#define E_ 8
#define D_ 1024
#define H_ 4096
#define O_ 1024
#define B_ 4096
#define MAXROWS 9216          // 8192 rows + per-expert padding to 128, <= 72 tiles
#define NTILES  72            // MAXROWS / 128

// ---------------- static device scratch (no allocations allowed) ----------------
__device__ __half g_h [(size_t)MAXROWS * H_];   // gelu(x@W1+b1), half
__device__ __half g_xa[(size_t)MAXROWS * D_];   // gathered x rows, half
__device__ __half g_wt[(size_t)E_ * D_ * H_];   // transposed weights [e][n][k] half (reused)
__device__ int    g_tok[MAXROWS];
__device__ float  g_wgt[MAXROWS];
__device__ int    g_counts[E_];
__device__ int    g_tile_expert[NTILES];
__device__ float  g_probs[(size_t)B_ * E_];
__device__ int    g_topk[B_ * 2];
__device__ float  g_topw[B_ * 2];

// ---------------- helpers ----------------
__device__ __forceinline__ void cp16(void* s, const void* g) {
    uint32_t sa = (uint32_t)__cvta_generic_to_shared(s);
    asm volatile("cp.async.cg.shared.global [%0], [%1], 16;\n" :: "r"(sa), "l"(g));
}
#define CP_COMMIT() asm volatile("cp.async.commit_group;\n")

__device__ __forceinline__ uint32_t smem_u32(const void* p) {
    return (uint32_t)__cvta_generic_to_shared(p);
}

// ---------------- init: zero output + counters ----------------
__global__ void init_kernel(float* __restrict__ out) {
    size_t i = (size_t)blockIdx.x * blockDim.x + threadIdx.x;   // B_*O_/4 float4s
    ((float4*)out)[i] = make_float4(0.f, 0.f, 0.f, 0.f);
    if (blockIdx.x == 0 && threadIdx.x < E_) g_counts[threadIdx.x] = 0;
}

// ---------------- transpose + f32->half: in [e][KD][ND] -> out [e][ND][KD] ------
template<int KD, int ND>
__global__ __launch_bounds__(256) void transpose_half_kernel(
    const float* __restrict__ in, __half* __restrict__ out)
{
    __shared__ float sm[32][33];
    int e = blockIdx.z;
    int n0 = blockIdx.x * 32, k0 = blockIdx.y * 32;
    int tx = threadIdx.x & 31, ty = threadIdx.x >> 5;   // 32 x 8
    const float* ine = in + (size_t)e * KD * ND;
    #pragma unroll
    for (int i = 0; i < 4; ++i)
        sm[ty + i * 8][tx] = ine[(size_t)(k0 + ty + i * 8) * ND + n0 + tx];
    __syncthreads();
    __half2* oute = (__half2*)(out + (size_t)e * ND * KD);
    int wk2 = threadIdx.x & 15;          // half2 index along k
    int wn  = threadIdx.x >> 4;          // 0..15
    #pragma unroll
    for (int i = 0; i < 2; ++i) {
        int n = wn + i * 16;
        oute[(size_t)(n0 + n) * (KD / 2) + (k0 >> 1) + wk2] =
            __floats2half2_rn(sm[wk2 * 2][n], sm[wk2 * 2 + 1][n]);
    }
}

// ---------------- router: 1 warp per token (proven R1) ----------------
__global__ __launch_bounds__(256) void router_kernel(
    const float* __restrict__ x, const float* __restrict__ gw, const float* __restrict__ gb)
{
    __shared__ float4 sgw[E_ * D_ / 4];    // 32 KB gate matrix
    int tid = threadIdx.x;
    for (int i = tid; i < E_ * D_ / 4; i += 256) sgw[i] = ((const float4*)gw)[i];
    __syncthreads();

    int warp = tid >> 5, lane = tid & 31;
    int t = blockIdx.x * 8 + warp;
    const float4* xr = (const float4*)(x + (size_t)t * D_);

    float acc[E_];
    #pragma unroll
    for (int e = 0; e < E_; ++e) acc[e] = 0.f;

    #pragma unroll
    for (int i = 0; i < D_ / 128; ++i) {
        float4 xv = xr[lane + 32 * i];
        #pragma unroll
        for (int e = 0; e < E_; ++e) {
            float4 g = sgw[e * (D_ / 4) + lane + 32 * i];
            acc[e] += xv.x * g.x + xv.y * g.y + xv.z * g.z + xv.w * g.w;
        }
    }
    #pragma unroll
    for (int e = 0; e < E_; ++e)
        #pragma unroll
        for (int o = 16; o; o >>= 1) acc[e] += __shfl_down_sync(0xffffffffu, acc[e], o);

    if (lane == 0) {
        float l[E_], m = -1e30f;
        #pragma unroll
        for (int e = 0; e < E_; ++e) { l[e] = acc[e] + gb[e]; m = fmaxf(m, l[e]); }
        float p[E_], s = 0.f;
        #pragma unroll
        for (int e = 0; e < E_; ++e) { p[e] = expf(l[e] - m); s += p[e]; }
        float inv = 1.f / s;
        int i0 = 0; float m0 = -1.f;
        #pragma unroll
        for (int e = 0; e < E_; ++e) {
            p[e] *= inv;
            g_probs[(size_t)t * E_ + e] = p[e];
            if (p[e] > m0) { m0 = p[e]; i0 = e; }
        }
        int i1 = -1; float m1 = -1.f;
        #pragma unroll
        for (int e = 0; e < E_; ++e)
            if (e != i0 && p[e] > m1) { m1 = p[e]; i1 = e; }
        float inv2 = 1.f / (m0 + m1 + 1e-9f);
        g_topk[t * 2 + 0] = i0;  g_topw[t * 2 + 0] = m0 * inv2;
        g_topk[t * 2 + 1] = i1;  g_topw[t * 2 + 1] = m1 * inv2;
        atomicAdd(&g_counts[i0], 1);
        atomicAdd(&g_counts[i1], 1);
    }
}

// ---------------- setup: offsets, tile map, scatter, pads (proven R1) -----------
__global__ void setup_kernel() {
    __shared__ int offs[E_], cnt[E_], padc[E_], cur[E_];
    int tid = threadIdx.x;
    if (tid == 0) {
        int acc = 0;
        for (int e = 0; e < E_; ++e) {
            cnt[e] = g_counts[e];
            offs[e] = acc;
            padc[e] = ((cnt[e] + 127) >> 7) << 7;
            acc += padc[e];
        }
        int tt = 0;
        for (int e = 0; e < E_; ++e)
            for (int j = 0; j < (padc[e] >> 7); ++j) g_tile_expert[tt++] = e;
        for (; tt < NTILES; ++tt) g_tile_expert[tt] = -1;
    }
    if (tid < E_) cur[tid] = 0;
    __syncthreads();

    for (int idx = tid; idx < B_ * 2; idx += blockDim.x) {
        int t = idx >> 1;
        int e = g_topk[idx];
        int pos = offs[e] + atomicAdd(&cur[e], 1);
        g_tok[pos] = t;
        g_wgt[pos] = g_topw[idx];
    }
    for (int e = 0; e < E_; ++e)
        for (int j = cnt[e] + tid; j < padc[e]; j += blockDim.x) {
            g_tok[offs[e] + j] = 0;
            g_wgt[offs[e] + j] = 0.f;
        }
}

// ---------------- gather x rows -> half into g_xa ----------------
__global__ __launch_bounds__(256) void gather_kernel(const float* __restrict__ x) {
    int tile = blockIdx.x;
    if (g_tile_expert[tile] < 0) return;
    int r0 = tile * 128 + blockIdx.y * 16;    // 16 rows per block
    for (int r = r0; r < r0 + 16; ++r) {
        const float4* src = (const float4*)(x + (size_t)g_tok[r] * D_);
        __half2* dst = (__half2*)(g_xa + (size_t)r * D_);
        int j = threadIdx.x;                   // D_/4 = 256 float4 per row
        float4 v = src[j];
        dst[j * 2 + 0] = __floats2half2_rn(v.x, v.y);
        dst[j * 2 + 1] = __floats2half2_rn(v.z, v.w);
    }
}

// ---------------- grouped FP16 GEMM (BM=BN=128, BK=32, 256 threads) ----------------
// A: [row][k] half (k-contiguous).  W: [e][n][k] half (k-contiguous).
// SMEM rows: 32 data halves + 8 pad = 20 uint32 per row (conflict-free at 80B pitch).
// A-fragments AND B-fragments via ldmatrix.x4 (B non-trans: lane(gid,tig) gets
// B[n=gid][k=tig*2..+1], exactly the mma col-major fragment).
// FIRST:  g_h[row] = half(gelu(A@W1 + b1))
// !FIRST: out[tok[row]] += wgt[row] * (A@W2 + b2)   (atomicAdd; pads have wgt==0)
template<int KDIM, int NTOT, bool FIRST>
__global__ __launch_bounds__(256, 2) void moe_gemm_h(
    const __half* __restrict__ A,
    const __half* __restrict__ W,
    const float* __restrict__ bias,
    float* __restrict__ out)
{
    int e = g_tile_expert[blockIdx.y];
    if (e < 0) return;
    const int row0 = blockIdx.y * 128;
    const int n0   = blockIdx.x * 128;
    const int tid  = threadIdx.x;

    __shared__ uint32_t As[2][128][20];   // 10240 B per buffer
    __shared__ uint32_t Bs[2][128][20];
    __shared__ int   s_tok[128];
    __shared__ float s_wgt[128];

    if (!FIRST && tid < 128) { s_tok[tid] = g_tok[row0 + tid]; s_wgt[tid] = g_wgt[row0 + tid]; }

    const __half* We = W + (size_t)e * NTOT * KDIM;   // [n][k]

    auto load_tile = [&](int kt, int buf) {
        const int kof = kt * 32;
        #pragma unroll
        for (int j = 0; j < 4; ++j) {
            int id = tid + j * 256;                 // 0..1023
            if (id < 512) {                         // A: 128 rows x 4 chunks(16B)
                int r = id >> 2, g = id & 3;
                cp16(&As[buf][r][g * 4], A + (size_t)(row0 + r) * KDIM + kof + g * 8);
            } else {                                // B: 128 n-rows x 4 chunks
                int id2 = id - 512;
                int r = id2 >> 2, g = id2 & 3;
                cp16(&Bs[buf][r][g * 4], We + (size_t)(n0 + r) * KDIM + kof + g * 8);
            }
        }
    };

    const int warp = tid >> 5, lane = tid & 31;
    const int wm = (warp & 3) * 32;   // 4 warps along M
    const int wn = (warp >> 2) * 64;  // 2 warps along N
    const int gid = lane >> 2, tig = lane & 3;

    // ldmatrix.x4 lane address for A: lanes 0-15 -> rows(+mf), cols kk; 16-31 -> cols kk+8
    const int lrow = lane & 15, lhi = lane >> 4;
    const uint32_t as_s = smem_u32(&As[0][0][0]);
    const uint32_t a_lane = as_s + (uint32_t)(wm + lrow) * 80u + (uint32_t)lhi * 16u;

    // ldmatrix.x4 lane address for B: 4 matrices per instr =
    //   m0: rows n = base+0..7  @ +kk      -> b[nf][0]
    //   m1: rows n = base+0..7  @ +kk+8    -> b[nf][1]
    //   m2: rows n = base+8..15 @ +kk      -> b[nf+1][0]
    //   m3: rows n = base+8..15 @ +kk+8    -> b[nf+1][1]
    const uint32_t bs_s = smem_u32(&Bs[0][0][0]);
    const uint32_t b_lane = bs_s
        + (uint32_t)(wn + (lane & 7) + ((lane >> 4) & 1) * 8) * 80u   // n-row
        + (uint32_t)((lane >> 3) & 1) * 16u;                          // k +8 halves

    float acc[2][8][4];
    #pragma unroll
    for (int mf = 0; mf < 2; ++mf)
        #pragma unroll
        for (int nf = 0; nf < 8; ++nf)
            #pragma unroll
            for (int i = 0; i < 4; ++i) acc[mf][nf][i] = 0.f;

    constexpr int KT = KDIM / 32;
    load_tile(0, 0);
    CP_COMMIT();

    for (int kt = 0; kt < KT; ++kt) {
        int cb = kt & 1;
        if (kt + 1 < KT) {
            load_tile(kt + 1, cb ^ 1);
            CP_COMMIT();
            asm volatile("cp.async.wait_group 1;\n");
        } else {
            asm volatile("cp.async.wait_group 0;\n");
        }
        __syncthreads();

        #pragma unroll
        for (int kk = 0; kk < 32; kk += 16) {
            uint32_t a[2][4], b[8][2];
            #pragma unroll
            for (int mf = 0; mf < 2; ++mf) {
                uint32_t addr = a_lane + (uint32_t)cb * 10240u
                              + (uint32_t)mf * 1280u + (uint32_t)kk * 2u;
                asm volatile(
                    "ldmatrix.sync.aligned.m8n8.x4.shared.b16 {%0,%1,%2,%3}, [%4];"
                    : "=r"(a[mf][0]), "=r"(a[mf][1]), "=r"(a[mf][2]), "=r"(a[mf][3])
                    : "r"(addr));
            }
            #pragma unroll
            for (int nf = 0; nf < 8; nf += 2) {
                uint32_t addr = b_lane + (uint32_t)cb * 10240u
                              + (uint32_t)nf * 640u + (uint32_t)kk * 2u;
                asm volatile(
                    "ldmatrix.sync.aligned.m8n8.x4.shared.b16 {%0,%1,%2,%3}, [%4];"
                    : "=r"(b[nf][0]), "=r"(b[nf][1]), "=r"(b[nf + 1][0]), "=r"(b[nf + 1][1])
                    : "r"(addr));
            }
            #pragma unroll
            for (int mf = 0; mf < 2; ++mf)
                #pragma unroll
                for (int nf = 0; nf < 8; ++nf)
                    asm volatile(
                        "mma.sync.aligned.m16n8k16.row.col.f32.f16.f16.f32 "
                        "{%0,%1,%2,%3},{%4,%5,%6,%7},{%8,%9},{%0,%1,%2,%3};\n"
                        : "+f"(acc[mf][nf][0]), "+f"(acc[mf][nf][1]),
                          "+f"(acc[mf][nf][2]), "+f"(acc[mf][nf][3])
                        : "r"(a[mf][0]), "r"(a[mf][1]), "r"(a[mf][2]), "r"(a[mf][3]),
                          "r"(b[nf][0]), "r"(b[nf][1]));
        }
        __syncthreads();
    }

    // -------- epilogue (c0,c1: row gid, cols tig*2+{0,1}; c2,c3: row gid+8) --------
    #pragma unroll
    for (int mf = 0; mf < 2; ++mf) {
        int rl = wm + mf * 16 + gid;
        #pragma unroll
        for (int nf = 0; nf < 8; ++nf) {
            int gc = n0 + wn + nf * 8 + tig * 2;
            float v00 = acc[mf][nf][0] + bias[e * NTOT + gc];
            float v01 = acc[mf][nf][1] + bias[e * NTOT + gc + 1];
            float v10 = acc[mf][nf][2] + bias[e * NTOT + gc];
            float v11 = acc[mf][nf][3] + bias[e * NTOT + gc + 1];
            if constexpr (FIRST) {
                v00 = 0.5f * v00 * (1.f + erff(v00 * 0.70710678118654752f));
                v01 = 0.5f * v01 * (1.f + erff(v01 * 0.70710678118654752f));
                v10 = 0.5f * v10 * (1.f + erff(v10 * 0.70710678118654752f));
                v11 = 0.5f * v11 * (1.f + erff(v11 * 0.70710678118654752f));
                *(__half2*)&g_h[(size_t)(row0 + rl)     * H_ + gc] = __floats2half2_rn(v00, v01);
                *(__half2*)&g_h[(size_t)(row0 + rl + 8) * H_ + gc] = __floats2half2_rn(v10, v11);
            } else {
                float w0 = s_wgt[rl];     int t0 = s_tok[rl];
                float w8 = s_wgt[rl + 8]; int t8 = s_tok[rl + 8];
                atomicAdd(&out[(size_t)t0 * O_ + gc    ], w0 * v00);
                atomicAdd(&out[(size_t)t0 * O_ + gc + 1], w0 * v01);
                atomicAdd(&out[(size_t)t8 * O_ + gc    ], w8 * v10);
                atomicAdd(&out[(size_t)t8 * O_ + gc + 1], w8 * v11);
            }
        }
    }
}

// ---------------- aux loss: deterministic fixed-order reduction (proven R1) -----
__global__ void aux_kernel(float* __restrict__ out, int aux_idx) {
    __shared__ float sm[256 * E_];
    int tid = threadIdx.x;
    float ps[E_];
    #pragma unroll
    for (int e = 0; e < E_; ++e) ps[e] = 0.f;
    for (int t = tid; t < B_; t += 256)
        #pragma unroll
        for (int e = 0; e < E_; ++e) ps[e] += g_probs[(size_t)t * E_ + e];
    #pragma unroll
    for (int e = 0; e < E_; ++e) sm[tid * E_ + e] = ps[e];
    __syncthreads();
    for (int o = 128; o; o >>= 1) {
        if (tid < o)
            #pragma unroll
            for (int e = 0; e < E_; ++e) sm[tid * E_ + e] += sm[(tid + o) * E_ + e];
        __syncthreads();
    }
    if (tid == 0) {
        float aux = 0.f;
        #pragma unroll
        for (int e = 0; e < E_; ++e) {
            float f = (float)g_counts[e] * (1.f / B_);
            float p = sm[e] * (1.f / B_);
            aux += f * p;
        }
        out[aux_idx] = aux * (0.01f * E_);
    }
}

// ---------------- launch ----------------
extern "C" void kernel_launch(void* const* d_in, const int* in_sizes, int n_in,
                              void* d_out, int out_size)
{
    const float* x  = (const float*)d_in[0];
    const float* w1 = (const float*)d_in[1];
    const float* b1 = (const float*)d_in[2];
    const float* w2 = (const float*)d_in[3];
    const float* b2 = (const float*)d_in[4];
    const float* gw = (const float*)d_in[5];
    const float* gb = (const float*)d_in[6];
    float* out = (float*)d_out;

    __half* p_xa; cudaGetSymbolAddress((void**)&p_xa, g_xa);
    __half* p_h;  cudaGetSymbolAddress((void**)&p_h,  g_h);
    __half* p_wt; cudaGetSymbolAddress((void**)&p_wt, g_wt);

    init_kernel<<<(B_ * O_) / 1024, 256>>>(out);
    router_kernel<<<B_ / 8, 256>>>(x, gw, gb);
    setup_kernel<<<1, 256>>>();
    gather_kernel<<<dim3(NTILES, 8), 256>>>(x);

    // g_wt reused: w1^T for GEMM1, then w2^T for GEMM2 (launches serial on one stream)
    transpose_half_kernel<D_, H_><<<dim3(H_ / 32, D_ / 32, E_), 256>>>(w1, p_wt);
    moe_gemm_h<D_, H_, true ><<<dim3(H_ / 128, NTILES), 256>>>(p_xa, p_wt, b1, out);
    transpose_half_kernel<H_, O_><<<dim3(O_ / 32, H_ / 32, E_), 256>>>(w2, p_wt);
    moe_gemm_h<H_, O_, false><<<dim3(O_ / 128, NTILES), 256>>>(p_h, p_wt, b2, out);

    aux_kernel<<<1, 256>>>(out, out_size - 1);
}

// round 9
// speedup vs baseline: 2.0103x; 1.0088x over previous
#include <cuda_runtime.h>
#include <cuda_fp16.h>
#include <cstdint>

#define E_ 8
#define D_ 1024
#define H_ 4096
#define O_ 1024
#define B_ 4096
#define MAXROWS 9216          // 8192 rows + per-expert padding to 128, <= 72 tiles
#define NTILES  72            // MAXROWS / 128

// ---------------- static device scratch (no allocations allowed) ----------------
__device__ __half g_h [(size_t)MAXROWS * H_];   // gelu(x@W1+b1), half
__device__ __half g_xa[(size_t)MAXROWS * D_];   // gathered x rows, half
__device__ __half g_wt[(size_t)E_ * D_ * H_];   // transposed weights [e][n][k] half (reused)
__device__ int    g_tok[MAXROWS];
__device__ float  g_wgt[MAXROWS];
__device__ int    g_counts[E_];                 // zero at start of every run (re-zeroed by setup)
__device__ int    g_cnt_saved[E_];              // counts snapshot for aux_kernel
__device__ int    g_tile_expert[NTILES];
__device__ float  g_probs[(size_t)B_ * E_];
__device__ int    g_topk[B_ * 2];
__device__ float  g_topw[B_ * 2];

// ---------------- helpers ----------------
__device__ __forceinline__ void cp16(void* s, const void* g) {
    uint32_t sa = (uint32_t)__cvta_generic_to_shared(s);
    asm volatile("cp.async.cg.shared.global [%0], [%1], 16;\n" :: "r"(sa), "l"(g));
}
#define CP_COMMIT() asm volatile("cp.async.commit_group;\n")

__device__ __forceinline__ uint32_t smem_u32(const void* p) {
    return (uint32_t)__cvta_generic_to_shared(p);
}

// ---------------- router: 1 warp per token; also zeroes its slice of out ---------
__global__ __launch_bounds__(256) void router_kernel(
    const float* __restrict__ x, const float* __restrict__ gw, const float* __restrict__ gb,
    float* __restrict__ out)
{
    // zero out rows [bid*8, bid*8+8) — replaces init_kernel (gemm2 runs much later)
    {
        float4* o4 = (float4*)(out + (size_t)blockIdx.x * 8 * O_);
        #pragma unroll
        for (int i = 0; i < 8; ++i)
            o4[threadIdx.x + i * 256] = make_float4(0.f, 0.f, 0.f, 0.f);
    }

    __shared__ float4 sgw[E_ * D_ / 4];    // 32 KB gate matrix
    int tid = threadIdx.x;
    for (int i = tid; i < E_ * D_ / 4; i += 256) sgw[i] = ((const float4*)gw)[i];
    __syncthreads();

    int warp = tid >> 5, lane = tid & 31;
    int t = blockIdx.x * 8 + warp;
    const float4* xr = (const float4*)(x + (size_t)t * D_);

    float acc[E_];
    #pragma unroll
    for (int e = 0; e < E_; ++e) acc[e] = 0.f;

    #pragma unroll
    for (int i = 0; i < D_ / 128; ++i) {
        float4 xv = xr[lane + 32 * i];
        #pragma unroll
        for (int e = 0; e < E_; ++e) {
            float4 g = sgw[e * (D_ / 4) + lane + 32 * i];
            acc[e] += xv.x * g.x + xv.y * g.y + xv.z * g.z + xv.w * g.w;
        }
    }
    #pragma unroll
    for (int e = 0; e < E_; ++e)
        #pragma unroll
        for (int o = 16; o; o >>= 1) acc[e] += __shfl_down_sync(0xffffffffu, acc[e], o);

    if (lane == 0) {
        float l[E_], m = -1e30f;
        #pragma unroll
        for (int e = 0; e < E_; ++e) { l[e] = acc[e] + gb[e]; m = fmaxf(m, l[e]); }
        float p[E_], s = 0.f;
        #pragma unroll
        for (int e = 0; e < E_; ++e) { p[e] = expf(l[e] - m); s += p[e]; }
        float inv = 1.f / s;
        int i0 = 0; float m0 = -1.f;
        #pragma unroll
        for (int e = 0; e < E_; ++e) {
            p[e] *= inv;
            g_probs[(size_t)t * E_ + e] = p[e];
            if (p[e] > m0) { m0 = p[e]; i0 = e; }
        }
        int i1 = -1; float m1 = -1.f;
        #pragma unroll
        for (int e = 0; e < E_; ++e)
            if (e != i0 && p[e] > m1) { m1 = p[e]; i1 = e; }
        float inv2 = 1.f / (m0 + m1 + 1e-9f);
        g_topk[t * 2 + 0] = i0;  g_topw[t * 2 + 0] = m0 * inv2;
        g_topk[t * 2 + 1] = i1;  g_topw[t * 2 + 1] = m1 * inv2;
        atomicAdd(&g_counts[i0], 1);
        atomicAdd(&g_counts[i1], 1);
    }
}

// ---------------- setup: offsets, tile map, scatter, pads; resets g_counts ------
__global__ void setup_kernel() {
    __shared__ int offs[E_], cnt[E_], padc[E_], cur[E_];
    int tid = threadIdx.x;
    if (tid == 0) {
        int acc = 0;
        for (int e = 0; e < E_; ++e) {
            cnt[e] = g_counts[e];
            offs[e] = acc;
            padc[e] = ((cnt[e] + 127) >> 7) << 7;
            acc += padc[e];
        }
        int tt = 0;
        for (int e = 0; e < E_; ++e)
            for (int j = 0; j < (padc[e] >> 7); ++j) g_tile_expert[tt++] = e;
        for (; tt < NTILES; ++tt) g_tile_expert[tt] = -1;
    }
    if (tid < E_) cur[tid] = 0;
    __syncthreads();

    if (tid < E_) {                      // snapshot for aux, reset for next replay
        g_cnt_saved[tid] = cnt[tid];
        g_counts[tid] = 0;
    }

    for (int idx = tid; idx < B_ * 2; idx += blockDim.x) {
        int t = idx >> 1;
        int e = g_topk[idx];
        int pos = offs[e] + atomicAdd(&cur[e], 1);
        g_tok[pos] = t;
        g_wgt[pos] = g_topw[idx];
    }
    for (int e = 0; e < E_; ++e)
        for (int j = cnt[e] + tid; j < padc[e]; j += blockDim.x) {
            g_tok[offs[e] + j] = 0;
            g_wgt[offs[e] + j] = 0.f;
        }
}

// ---------------- prep1: fused gather(x->half g_xa)  +  transpose w1 -> g_wt ----
// blocks [0, 576): gather;  blocks [576, 576+32768): w1 transpose (KD=D_, ND=H_)
#define GATHER_BLOCKS 576
__global__ __launch_bounds__(256) void prep1_kernel(
    const float* __restrict__ x, const float* __restrict__ w1, __half* __restrict__ wt)
{
    int id = blockIdx.x;
    if (id < GATHER_BLOCKS) {
        int tile = id >> 3;
        if (g_tile_expert[tile] < 0) return;
        int r0 = tile * 128 + (id & 7) * 16;
        for (int r = r0; r < r0 + 16; ++r) {
            const float4* src = (const float4*)(x + (size_t)g_tok[r] * D_);
            __half2* dst = (__half2*)(g_xa + (size_t)r * D_);
            int j = threadIdx.x;
            float4 v = src[j];
            dst[j * 2 + 0] = __floats2half2_rn(v.x, v.y);
            dst[j * 2 + 1] = __floats2half2_rn(v.z, v.w);
        }
    } else {
        // transpose tile: in [e][D_][H_] f32 -> out [e][H_][D_] half
        __shared__ float sm[32][33];
        int id2 = id - GATHER_BLOCKS;                 // [0, 8*32*128)
        int e = id2 >> 12;
        int rem = id2 & 4095;
        int n0 = (rem & 127) * 32;                    // along H_
        int k0 = (rem >> 7) * 32;                     // along D_
        int tx = threadIdx.x & 31, ty = threadIdx.x >> 5;
        const float* ine = w1 + (size_t)e * D_ * H_;
        #pragma unroll
        for (int i = 0; i < 4; ++i)
            sm[ty + i * 8][tx] = ine[(size_t)(k0 + ty + i * 8) * H_ + n0 + tx];
        __syncthreads();
        __half2* oute = (__half2*)(wt + (size_t)e * H_ * D_);
        int wk2 = threadIdx.x & 15;
        int wn  = threadIdx.x >> 4;
        #pragma unroll
        for (int i = 0; i < 2; ++i) {
            int n = wn + i * 16;
            oute[(size_t)(n0 + n) * (D_ / 2) + (k0 >> 1) + wk2] =
                __floats2half2_rn(sm[wk2 * 2][n], sm[wk2 * 2 + 1][n]);
        }
    }
}

// ---------------- transpose + f32->half (prep2 for w2): [e][KD][ND] -> [e][ND][KD]
template<int KD, int ND>
__global__ __launch_bounds__(256) void transpose_half_kernel(
    const float* __restrict__ in, __half* __restrict__ out)
{
    __shared__ float sm[32][33];
    int e = blockIdx.z;
    int n0 = blockIdx.x * 32, k0 = blockIdx.y * 32;
    int tx = threadIdx.x & 31, ty = threadIdx.x >> 5;
    const float* ine = in + (size_t)e * KD * ND;
    #pragma unroll
    for (int i = 0; i < 4; ++i)
        sm[ty + i * 8][tx] = ine[(size_t)(k0 + ty + i * 8) * ND + n0 + tx];
    __syncthreads();
    __half2* oute = (__half2*)(out + (size_t)e * ND * KD);
    int wk2 = threadIdx.x & 15;
    int wn  = threadIdx.x >> 4;
    #pragma unroll
    for (int i = 0; i < 2; ++i) {
        int n = wn + i * 16;
        oute[(size_t)(n0 + n) * (KD / 2) + (k0 >> 1) + wk2] =
            __floats2half2_rn(sm[wk2 * 2][n], sm[wk2 * 2 + 1][n]);
    }
}

// ---------------- grouped FP16 GEMM (BM=BN=128, BK=32, 256 threads) ----------------
// BYTE-IDENTICAL compute to the passing R7 kernel (ldmatrix A + ldmatrix B).
template<int KDIM, int NTOT, bool FIRST>
__global__ __launch_bounds__(256, 2) void moe_gemm_h(
    const __half* __restrict__ A,
    const __half* __restrict__ W,
    const float* __restrict__ bias,
    float* __restrict__ out)
{
    int e = g_tile_expert[blockIdx.y];
    if (e < 0) return;
    const int row0 = blockIdx.y * 128;
    const int n0   = blockIdx.x * 128;
    const int tid  = threadIdx.x;

    __shared__ uint32_t As[2][128][20];   // 10240 B per buffer
    __shared__ uint32_t Bs[2][128][20];
    __shared__ int   s_tok[128];
    __shared__ float s_wgt[128];

    if (!FIRST && tid < 128) { s_tok[tid] = g_tok[row0 + tid]; s_wgt[tid] = g_wgt[row0 + tid]; }

    const __half* We = W + (size_t)e * NTOT * KDIM;   // [n][k]

    auto load_tile = [&](int kt, int buf) {
        const int kof = kt * 32;
        #pragma unroll
        for (int j = 0; j < 4; ++j) {
            int id = tid + j * 256;
            if (id < 512) {
                int r = id >> 2, g = id & 3;
                cp16(&As[buf][r][g * 4], A + (size_t)(row0 + r) * KDIM + kof + g * 8);
            } else {
                int id2 = id - 512;
                int r = id2 >> 2, g = id2 & 3;
                cp16(&Bs[buf][r][g * 4], We + (size_t)(n0 + r) * KDIM + kof + g * 8);
            }
        }
    };

    const int warp = tid >> 5, lane = tid & 31;
    const int wm = (warp & 3) * 32;
    const int wn = (warp >> 2) * 64;
    const int gid = lane >> 2, tig = lane & 3;

    const int lrow = lane & 15, lhi = lane >> 4;
    const uint32_t as_s = smem_u32(&As[0][0][0]);
    const uint32_t a_lane = as_s + (uint32_t)(wm + lrow) * 80u + (uint32_t)lhi * 16u;

    const uint32_t bs_s = smem_u32(&Bs[0][0][0]);
    const uint32_t b_lane = bs_s
        + (uint32_t)(wn + (lane & 7) + ((lane >> 4) & 1) * 8) * 80u
        + (uint32_t)((lane >> 3) & 1) * 16u;

    float acc[2][8][4];
    #pragma unroll
    for (int mf = 0; mf < 2; ++mf)
        #pragma unroll
        for (int nf = 0; nf < 8; ++nf)
            #pragma unroll
            for (int i = 0; i < 4; ++i) acc[mf][nf][i] = 0.f;

    constexpr int KT = KDIM / 32;
    load_tile(0, 0);
    CP_COMMIT();

    for (int kt = 0; kt < KT; ++kt) {
        int cb = kt & 1;
        if (kt + 1 < KT) {
            load_tile(kt + 1, cb ^ 1);
            CP_COMMIT();
            asm volatile("cp.async.wait_group 1;\n");
        } else {
            asm volatile("cp.async.wait_group 0;\n");
        }
        __syncthreads();

        #pragma unroll
        for (int kk = 0; kk < 32; kk += 16) {
            uint32_t a[2][4], b[8][2];
            #pragma unroll
            for (int mf = 0; mf < 2; ++mf) {
                uint32_t addr = a_lane + (uint32_t)cb * 10240u
                              + (uint32_t)mf * 1280u + (uint32_t)kk * 2u;
                asm volatile(
                    "ldmatrix.sync.aligned.m8n8.x4.shared.b16 {%0,%1,%2,%3}, [%4];"
                    : "=r"(a[mf][0]), "=r"(a[mf][1]), "=r"(a[mf][2]), "=r"(a[mf][3])
                    : "r"(addr));
            }
            #pragma unroll
            for (int nf = 0; nf < 8; nf += 2) {
                uint32_t addr = b_lane + (uint32_t)cb * 10240u
                              + (uint32_t)nf * 640u + (uint32_t)kk * 2u;
                asm volatile(
                    "ldmatrix.sync.aligned.m8n8.x4.shared.b16 {%0,%1,%2,%3}, [%4];"
                    : "=r"(b[nf][0]), "=r"(b[nf][1]), "=r"(b[nf + 1][0]), "=r"(b[nf + 1][1])
                    : "r"(addr));
            }
            #pragma unroll
            for (int mf = 0; mf < 2; ++mf)
                #pragma unroll
                for (int nf = 0; nf < 8; ++nf)
                    asm volatile(
                        "mma.sync.aligned.m16n8k16.row.col.f32.f16.f16.f32 "
                        "{%0,%1,%2,%3},{%4,%5,%6,%7},{%8,%9},{%0,%1,%2,%3};\n"
                        : "+f"(acc[mf][nf][0]), "+f"(acc[mf][nf][1]),
                          "+f"(acc[mf][nf][2]), "+f"(acc[mf][nf][3])
                        : "r"(a[mf][0]), "r"(a[mf][1]), "r"(a[mf][2]), "r"(a[mf][3]),
                          "r"(b[nf][0]), "r"(b[nf][1]));
        }
        __syncthreads();
    }

    #pragma unroll
    for (int mf = 0; mf < 2; ++mf) {
        int rl = wm + mf * 16 + gid;
        #pragma unroll
        for (int nf = 0; nf < 8; ++nf) {
            int gc = n0 + wn + nf * 8 + tig * 2;
            float v00 = acc[mf][nf][0] + bias[e * NTOT + gc];
            float v01 = acc[mf][nf][1] + bias[e * NTOT + gc + 1];
            float v10 = acc[mf][nf][2] + bias[e * NTOT + gc];
            float v11 = acc[mf][nf][3] + bias[e * NTOT + gc + 1];
            if constexpr (FIRST) {
                v00 = 0.5f * v00 * (1.f + erff(v00 * 0.70710678118654752f));
                v01 = 0.5f * v01 * (1.f + erff(v01 * 0.70710678118654752f));
                v10 = 0.5f * v10 * (1.f + erff(v10 * 0.70710678118654752f));
                v11 = 0.5f * v11 * (1.f + erff(v11 * 0.70710678118654752f));
                *(__half2*)&g_h[(size_t)(row0 + rl)     * H_ + gc] = __floats2half2_rn(v00, v01);
                *(__half2*)&g_h[(size_t)(row0 + rl + 8) * H_ + gc] = __floats2half2_rn(v10, v11);
            } else {
                float w0 = s_wgt[rl];     int t0 = s_tok[rl];
                float w8 = s_wgt[rl + 8]; int t8 = s_tok[rl + 8];
                atomicAdd(&out[(size_t)t0 * O_ + gc    ], w0 * v00);
                atomicAdd(&out[(size_t)t0 * O_ + gc + 1], w0 * v01);
                atomicAdd(&out[(size_t)t8 * O_ + gc    ], w8 * v10);
                atomicAdd(&out[(size_t)t8 * O_ + gc + 1], w8 * v11);
            }
        }
    }
}

// ---------------- aux loss: deterministic fixed-order reduction -----------------
__global__ void aux_kernel(float* __restrict__ out, int aux_idx) {
    __shared__ float sm[256 * E_];
    int tid = threadIdx.x;
    float ps[E_];
    #pragma unroll
    for (int e = 0; e < E_; ++e) ps[e] = 0.f;
    for (int t = tid; t < B_; t += 256)
        #pragma unroll
        for (int e = 0; e < E_; ++e) ps[e] += g_probs[(size_t)t * E_ + e];
    #pragma unroll
    for (int e = 0; e < E_; ++e) sm[tid * E_ + e] = ps[e];
    __syncthreads();
    for (int o = 128; o; o >>= 1) {
        if (tid < o)
            #pragma unroll
            for (int e = 0; e < E_; ++e) sm[tid * E_ + e] += sm[(tid + o) * E_ + e];
        __syncthreads();
    }
    if (tid == 0) {
        float aux = 0.f;
        #pragma unroll
        for (int e = 0; e < E_; ++e) {
            float f = (float)g_cnt_saved[e] * (1.f / B_);
            float p = sm[e] * (1.f / B_);
            aux += f * p;
        }
        out[aux_idx] = aux * (0.01f * E_);
    }
}

// ---------------- launch ----------------
extern "C" void kernel_launch(void* const* d_in, const int* in_sizes, int n_in,
                              void* d_out, int out_size)
{
    const float* x  = (const float*)d_in[0];
    const float* w1 = (const float*)d_in[1];
    const float* b1 = (const float*)d_in[2];
    const float* w2 = (const float*)d_in[3];
    const float* b2 = (const float*)d_in[4];
    const float* gw = (const float*)d_in[5];
    const float* gb = (const float*)d_in[6];
    float* out = (float*)d_out;

    __half* p_xa; cudaGetSymbolAddress((void**)&p_xa, g_xa);
    __half* p_h;  cudaGetSymbolAddress((void**)&p_h,  g_h);
    __half* p_wt; cudaGetSymbolAddress((void**)&p_wt, g_wt);

    // 1: router (also zeroes out);  2: setup (also resets g_counts)
    router_kernel<<<B_ / 8, 256>>>(x, gw, gb, out);
    setup_kernel<<<1, 256>>>();
    // 3: fused gather + w1 transpose
    prep1_kernel<<<GATHER_BLOCKS + E_ * (D_ / 32) * (H_ / 32), 256>>>(x, w1, p_wt);
    // 4: GEMM1  <- lands in the ncu capture slot
    moe_gemm_h<D_, H_, true ><<<dim3(H_ / 128, NTILES), 256>>>(p_xa, p_wt, b1, out);
    // 5: w2 transpose (reuses g_wt; launches are serial on one stream)
    transpose_half_kernel<H_, O_><<<dim3(O_ / 32, H_ / 32, E_), 256>>>(w2, p_wt);
    // 6: GEMM2
    moe_gemm_h<H_, O_, false><<<dim3(O_ / 128, NTILES), 256>>>(p_h, p_wt, b2, out);
    // 7: aux loss
    aux_kernel<<<1, 256>>>(out, out_size - 1);
}

// round 10
// speedup vs baseline: 2.0254x; 1.0075x over previous
#include <cuda_runtime.h>
#include <cuda_fp16.h>
#include <cstdint>

#define E_ 8
#define D_ 1024
#define H_ 4096
#define O_ 1024
#define B_ 4096
#define MAXROWS 9216          // 8192 rows + per-expert padding to 128, <= 72 tiles
#define NTILES  72            // MAXROWS / 128

// GEMM smem layout (uint32 indices): As[3][128][20] | Bs[3][128][20] | tok[128] | wgt[128]
#define STG_U32   2560        // 128*20
#define BS_OFF    7680        // 3*2560
#define TOK_OFF   15360
#define WGT_OFF   15488
#define GEMM_SMEM_BYTES (15616 * 4)   // 62464

// ---------------- static device scratch (no allocations allowed) ----------------
__device__ __half g_h  [(size_t)MAXROWS * H_];   // gelu(x@W1+b1), half
__device__ __half g_xa [(size_t)MAXROWS * D_];   // gathered x rows, half
__device__ __half g_w1t[(size_t)E_ * H_ * D_];   // w1^T [e][h][d] half
__device__ __half g_w2t[(size_t)E_ * O_ * H_];   // w2^T [e][o][h] half
__device__ int    g_tok[MAXROWS];
__device__ float  g_wgt[MAXROWS];
__device__ int    g_counts[E_];                  // zero at start of every run (re-zeroed by setup)
__device__ int    g_cnt_saved[E_];
__device__ int    g_tile_expert[NTILES];
__device__ float  g_probs[(size_t)B_ * E_];
__device__ int    g_topk[B_ * 2];
__device__ float  g_topw[B_ * 2];

// ---------------- helpers ----------------
__device__ __forceinline__ void cp16(void* s, const void* g) {
    uint32_t sa = (uint32_t)__cvta_generic_to_shared(s);
    asm volatile("cp.async.cg.shared.global [%0], [%1], 16;\n" :: "r"(sa), "l"(g));
}
#define CP_COMMIT() asm volatile("cp.async.commit_group;\n")

__device__ __forceinline__ uint32_t smem_u32(const void* p) {
    return (uint32_t)__cvta_generic_to_shared(p);
}

// ---------------- router: 1 warp per token; also zeroes its slice of out ---------
__global__ __launch_bounds__(256) void router_kernel(
    const float* __restrict__ x, const float* __restrict__ gw, const float* __restrict__ gb,
    float* __restrict__ out)
{
    {
        float4* o4 = (float4*)(out + (size_t)blockIdx.x * 8 * O_);
        #pragma unroll
        for (int i = 0; i < 8; ++i)
            o4[threadIdx.x + i * 256] = make_float4(0.f, 0.f, 0.f, 0.f);
    }

    __shared__ float4 sgw[E_ * D_ / 4];    // 32 KB gate matrix
    int tid = threadIdx.x;
    for (int i = tid; i < E_ * D_ / 4; i += 256) sgw[i] = ((const float4*)gw)[i];
    __syncthreads();

    int warp = tid >> 5, lane = tid & 31;
    int t = blockIdx.x * 8 + warp;
    const float4* xr = (const float4*)(x + (size_t)t * D_);

    float acc[E_];
    #pragma unroll
    for (int e = 0; e < E_; ++e) acc[e] = 0.f;

    #pragma unroll
    for (int i = 0; i < D_ / 128; ++i) {
        float4 xv = xr[lane + 32 * i];
        #pragma unroll
        for (int e = 0; e < E_; ++e) {
            float4 g = sgw[e * (D_ / 4) + lane + 32 * i];
            acc[e] += xv.x * g.x + xv.y * g.y + xv.z * g.z + xv.w * g.w;
        }
    }
    #pragma unroll
    for (int e = 0; e < E_; ++e)
        #pragma unroll
        for (int o = 16; o; o >>= 1) acc[e] += __shfl_down_sync(0xffffffffu, acc[e], o);

    if (lane == 0) {
        float l[E_], m = -1e30f;
        #pragma unroll
        for (int e = 0; e < E_; ++e) { l[e] = acc[e] + gb[e]; m = fmaxf(m, l[e]); }
        float p[E_], s = 0.f;
        #pragma unroll
        for (int e = 0; e < E_; ++e) { p[e] = expf(l[e] - m); s += p[e]; }
        float inv = 1.f / s;
        int i0 = 0; float m0 = -1.f;
        #pragma unroll
        for (int e = 0; e < E_; ++e) {
            p[e] *= inv;
            g_probs[(size_t)t * E_ + e] = p[e];
            if (p[e] > m0) { m0 = p[e]; i0 = e; }
        }
        int i1 = -1; float m1 = -1.f;
        #pragma unroll
        for (int e = 0; e < E_; ++e)
            if (e != i0 && p[e] > m1) { m1 = p[e]; i1 = e; }
        float inv2 = 1.f / (m0 + m1 + 1e-9f);
        g_topk[t * 2 + 0] = i0;  g_topw[t * 2 + 0] = m0 * inv2;
        g_topk[t * 2 + 1] = i1;  g_topw[t * 2 + 1] = m1 * inv2;
        atomicAdd(&g_counts[i0], 1);
        atomicAdd(&g_counts[i1], 1);
    }
}

// ---------------- setup: offsets, tile map, scatter, pads; resets g_counts ------
__global__ void setup_kernel() {
    __shared__ int offs[E_], cnt[E_], padc[E_], cur[E_];
    int tid = threadIdx.x;
    if (tid == 0) {
        int acc = 0;
        for (int e = 0; e < E_; ++e) {
            cnt[e] = g_counts[e];
            offs[e] = acc;
            padc[e] = ((cnt[e] + 127) >> 7) << 7;
            acc += padc[e];
        }
        int tt = 0;
        for (int e = 0; e < E_; ++e)
            for (int j = 0; j < (padc[e] >> 7); ++j) g_tile_expert[tt++] = e;
        for (; tt < NTILES; ++tt) g_tile_expert[tt] = -1;
    }
    if (tid < E_) cur[tid] = 0;
    __syncthreads();

    if (tid < E_) {
        g_cnt_saved[tid] = cnt[tid];
        g_counts[tid] = 0;
    }

    for (int idx = tid; idx < B_ * 2; idx += blockDim.x) {
        int t = idx >> 1;
        int e = g_topk[idx];
        int pos = offs[e] + atomicAdd(&cur[e], 1);
        g_tok[pos] = t;
        g_wgt[pos] = g_topw[idx];
    }
    for (int e = 0; e < E_; ++e)
        for (int j = cnt[e] + tid; j < padc[e]; j += blockDim.x) {
            g_tok[offs[e] + j] = 0;
            g_wgt[offs[e] + j] = 0.f;
        }
}

// ---------------- generic 32x32 transpose tile helper (f32 in -> half out) ------
template<int KD, int ND>
__device__ __forceinline__ void transpose_tile(
    const float* __restrict__ ine, __half* __restrict__ oute_h, int n0, int k0)
{
    __shared__ float sm[32][33];
    int tx = threadIdx.x & 31, ty = threadIdx.x >> 5;
    #pragma unroll
    for (int i = 0; i < 4; ++i)
        sm[ty + i * 8][tx] = ine[(size_t)(k0 + ty + i * 8) * ND + n0 + tx];
    __syncthreads();
    __half2* oute = (__half2*)oute_h;
    int wk2 = threadIdx.x & 15;
    int wn  = threadIdx.x >> 4;
    #pragma unroll
    for (int i = 0; i < 2; ++i) {
        int n = wn + i * 16;
        oute[(size_t)(n0 + n) * (KD / 2) + (k0 >> 1) + wk2] =
            __floats2half2_rn(sm[wk2 * 2][n], sm[wk2 * 2 + 1][n]);
    }
}

// ---------------- prep1: gather(x->g_xa) + w1^T -> g_w1t + w2^T -> g_w2t --------
// blocks [0,576): gather; [576, 576+32768): w1T; [576+32768, 576+65536): w2T
#define GATHER_BLOCKS 576
#define W1T_BLOCKS (E_ * (D_ / 32) * (H_ / 32))   // 32768
#define W2T_BLOCKS (E_ * (H_ / 32) * (O_ / 32))   // 32768
__global__ __launch_bounds__(256) void prep1_kernel(
    const float* __restrict__ x, const float* __restrict__ w1, const float* __restrict__ w2)
{
    int id = blockIdx.x;
    if (id < GATHER_BLOCKS) {
        int tile = id >> 3;
        if (g_tile_expert[tile] < 0) return;
        int r0 = tile * 128 + (id & 7) * 16;
        for (int r = r0; r < r0 + 16; ++r) {
            const float4* src = (const float4*)(x + (size_t)g_tok[r] * D_);
            __half2* dst = (__half2*)(g_xa + (size_t)r * D_);
            int j = threadIdx.x;
            float4 v = src[j];
            dst[j * 2 + 0] = __floats2half2_rn(v.x, v.y);
            dst[j * 2 + 1] = __floats2half2_rn(v.z, v.w);
        }
    } else if (id < GATHER_BLOCKS + W1T_BLOCKS) {
        int id2 = id - GATHER_BLOCKS;                 // [0, 8*32*128)
        int e = id2 >> 12;
        int rem = id2 & 4095;
        int n0 = (rem & 127) * 32;                    // along H_ (ND=H_, 128 tiles)
        int k0 = (rem >> 7) * 32;                     // along D_ (32 tiles)
        transpose_tile<D_, H_>(w1 + (size_t)e * D_ * H_,
                               g_w1t + (size_t)e * H_ * D_, n0, k0);
    } else {
        int id3 = id - GATHER_BLOCKS - W1T_BLOCKS;    // [0, 8*128*32)
        int e = id3 >> 12;
        int rem = id3 & 4095;
        int n0 = (rem & 31) * 32;                     // along O_ (ND=O_, 32 tiles)
        int k0 = (rem >> 5) * 32;                     // along H_ (128 tiles)
        transpose_tile<H_, O_>(w2 + (size_t)e * H_ * O_,
                               g_w2t + (size_t)e * O_ * H_, n0, k0);
    }
}

// ---------------- grouped FP16 GEMM: 3-stage cp.async ring, 1 barrier/iter ------
// A: [row][k] half.  W: [e][n][k] half.  Fragments/epilogue identical to R7/R9.
template<int KDIM, int NTOT, bool FIRST>
__global__ __launch_bounds__(256, 2) void moe_gemm_h(
    const __half* __restrict__ A,
    const __half* __restrict__ W,
    const float* __restrict__ bias,
    float* __restrict__ out)
{
    int e = g_tile_expert[blockIdx.y];
    if (e < 0) return;
    const int row0 = blockIdx.y * 128;
    const int n0   = blockIdx.x * 128;
    const int tid  = threadIdx.x;

    extern __shared__ uint32_t dsm[];
    uint32_t (*As)[128][20] = (uint32_t(*)[128][20])dsm;
    uint32_t (*Bs)[128][20] = (uint32_t(*)[128][20])(dsm + BS_OFF);
    int*   s_tok = (int*)(dsm + TOK_OFF);
    float* s_wgt = (float*)(dsm + WGT_OFF);

    if (!FIRST && tid < 128) { s_tok[tid] = g_tok[row0 + tid]; s_wgt[tid] = g_wgt[row0 + tid]; }

    const __half* We = W + (size_t)e * NTOT * KDIM;   // [n][k]

    auto load_tile = [&](int kt, int s) {
        const int kof = kt * 32;
        #pragma unroll
        for (int j = 0; j < 4; ++j) {
            int id = tid + j * 256;
            if (id < 512) {                         // A: 128 rows x 4 chunks(16B)
                int r = id >> 2, g = id & 3;
                cp16(&As[s][r][g * 4], A + (size_t)(row0 + r) * KDIM + kof + g * 8);
            } else {                                // B: 128 n-rows x 4 chunks
                int id2 = id - 512;
                int r = id2 >> 2, g = id2 & 3;
                cp16(&Bs[s][r][g * 4], We + (size_t)(n0 + r) * KDIM + kof + g * 8);
            }
        }
    };

    const int warp = tid >> 5, lane = tid & 31;
    const int wm = (warp & 3) * 32;
    const int wn = (warp >> 2) * 64;
    const int gid = lane >> 2, tig = lane & 3;

    const int lrow = lane & 15, lhi = lane >> 4;
    const uint32_t as_s = smem_u32(&As[0][0][0]);
    const uint32_t a_lane = as_s + (uint32_t)(wm + lrow) * 80u + (uint32_t)lhi * 16u;

    const uint32_t bs_s = smem_u32(&Bs[0][0][0]);
    const uint32_t b_lane = bs_s
        + (uint32_t)(wn + (lane & 7) + ((lane >> 4) & 1) * 8) * 80u
        + (uint32_t)((lane >> 3) & 1) * 16u;

    float acc[2][8][4];
    #pragma unroll
    for (int mf = 0; mf < 2; ++mf)
        #pragma unroll
        for (int nf = 0; nf < 8; ++nf)
            #pragma unroll
            for (int i = 0; i < 4; ++i) acc[mf][nf][i] = 0.f;

    constexpr int KT = KDIM / 32;
    load_tile(0, 0); CP_COMMIT();
    load_tile(1, 1); CP_COMMIT();

    int s = 0;
    for (int kt = 0; kt < KT; ++kt) {
        // stage kt resident after: <=1 pending (normal) / 0 pending (last iter)
        if (kt + 1 < KT) asm volatile("cp.async.wait_group 1;\n");
        else             asm volatile("cp.async.wait_group 0;\n");
        __syncthreads();   // all warps done reading stage (kt+2)%3 (= iter kt-1's stage)

        if (kt + 2 < KT) { load_tile(kt + 2, (kt + 2) % 3); CP_COMMIT(); }

        const uint32_t soff = (uint32_t)s * 10240u;
        #pragma unroll
        for (int kk = 0; kk < 32; kk += 16) {
            uint32_t a[2][4], b[8][2];
            #pragma unroll
            for (int mf = 0; mf < 2; ++mf) {
                uint32_t addr = a_lane + soff + (uint32_t)mf * 1280u + (uint32_t)kk * 2u;
                asm volatile(
                    "ldmatrix.sync.aligned.m8n8.x4.shared.b16 {%0,%1,%2,%3}, [%4];"
                    : "=r"(a[mf][0]), "=r"(a[mf][1]), "=r"(a[mf][2]), "=r"(a[mf][3])
                    : "r"(addr));
            }
            #pragma unroll
            for (int nf = 0; nf < 8; nf += 2) {
                uint32_t addr = b_lane + soff + (uint32_t)nf * 640u + (uint32_t)kk * 2u;
                asm volatile(
                    "ldmatrix.sync.aligned.m8n8.x4.shared.b16 {%0,%1,%2,%3}, [%4];"
                    : "=r"(b[nf][0]), "=r"(b[nf][1]), "=r"(b[nf + 1][0]), "=r"(b[nf + 1][1])
                    : "r"(addr));
            }
            #pragma unroll
            for (int mf = 0; mf < 2; ++mf)
                #pragma unroll
                for (int nf = 0; nf < 8; ++nf)
                    asm volatile(
                        "mma.sync.aligned.m16n8k16.row.col.f32.f16.f16.f32 "
                        "{%0,%1,%2,%3},{%4,%5,%6,%7},{%8,%9},{%0,%1,%2,%3};\n"
                        : "+f"(acc[mf][nf][0]), "+f"(acc[mf][nf][1]),
                          "+f"(acc[mf][nf][2]), "+f"(acc[mf][nf][3])
                        : "r"(a[mf][0]), "r"(a[mf][1]), "r"(a[mf][2]), "r"(a[mf][3]),
                          "r"(b[nf][0]), "r"(b[nf][1]));
        }
        s = (s + 1 == 3) ? 0 : s + 1;
    }

    #pragma unroll
    for (int mf = 0; mf < 2; ++mf) {
        int rl = wm + mf * 16 + gid;
        #pragma unroll
        for (int nf = 0; nf < 8; ++nf) {
            int gc = n0 + wn + nf * 8 + tig * 2;
            float v00 = acc[mf][nf][0] + bias[e * NTOT + gc];
            float v01 = acc[mf][nf][1] + bias[e * NTOT + gc + 1];
            float v10 = acc[mf][nf][2] + bias[e * NTOT + gc];
            float v11 = acc[mf][nf][3] + bias[e * NTOT + gc + 1];
            if constexpr (FIRST) {
                v00 = 0.5f * v00 * (1.f + erff(v00 * 0.70710678118654752f));
                v01 = 0.5f * v01 * (1.f + erff(v01 * 0.70710678118654752f));
                v10 = 0.5f * v10 * (1.f + erff(v10 * 0.70710678118654752f));
                v11 = 0.5f * v11 * (1.f + erff(v11 * 0.70710678118654752f));
                *(__half2*)&g_h[(size_t)(row0 + rl)     * H_ + gc] = __floats2half2_rn(v00, v01);
                *(__half2*)&g_h[(size_t)(row0 + rl + 8) * H_ + gc] = __floats2half2_rn(v10, v11);
            } else {
                float w0 = s_wgt[rl];     int t0 = s_tok[rl];
                float w8 = s_wgt[rl + 8]; int t8 = s_tok[rl + 8];
                atomicAdd(&out[(size_t)t0 * O_ + gc    ], w0 * v00);
                atomicAdd(&out[(size_t)t0 * O_ + gc + 1], w0 * v01);
                atomicAdd(&out[(size_t)t8 * O_ + gc    ], w8 * v10);
                atomicAdd(&out[(size_t)t8 * O_ + gc + 1], w8 * v11);
            }
        }
    }
}

// ---------------- aux loss: deterministic fixed-order reduction -----------------
__global__ void aux_kernel(float* __restrict__ out, int aux_idx) {
    __shared__ float sm[256 * E_];
    int tid = threadIdx.x;
    float ps[E_];
    #pragma unroll
    for (int e = 0; e < E_; ++e) ps[e] = 0.f;
    for (int t = tid; t < B_; t += 256)
        #pragma unroll
        for (int e = 0; e < E_; ++e) ps[e] += g_probs[(size_t)t * E_ + e];
    #pragma unroll
    for (int e = 0; e < E_; ++e) sm[tid * E_ + e] = ps[e];
    __syncthreads();
    for (int o = 128; o; o >>= 1) {
        if (tid < o)
            #pragma unroll
            for (int e = 0; e < E_; ++e) sm[tid * E_ + e] += sm[(tid + o) * E_ + e];
        __syncthreads();
    }
    if (tid == 0) {
        float aux = 0.f;
        #pragma unroll
        for (int e = 0; e < E_; ++e) {
            float f = (float)g_cnt_saved[e] * (1.f / B_);
            float p = sm[e] * (1.f / B_);
            aux += f * p;
        }
        out[aux_idx] = aux * (0.01f * E_);
    }
}

// ---------------- launch ----------------
extern "C" void kernel_launch(void* const* d_in, const int* in_sizes, int n_in,
                              void* d_out, int out_size)
{
    const float* x  = (const float*)d_in[0];
    const float* w1 = (const float*)d_in[1];
    const float* b1 = (const float*)d_in[2];
    const float* w2 = (const float*)d_in[3];
    const float* b2 = (const float*)d_in[4];
    const float* gw = (const float*)d_in[5];
    const float* gb = (const float*)d_in[6];
    float* out = (float*)d_out;

    __half* p_xa;  cudaGetSymbolAddress((void**)&p_xa,  g_xa);
    __half* p_h;   cudaGetSymbolAddress((void**)&p_h,   g_h);
    __half* p_w1t; cudaGetSymbolAddress((void**)&p_w1t, g_w1t);
    __half* p_w2t; cudaGetSymbolAddress((void**)&p_w2t, g_w2t);

    cudaFuncSetAttribute(moe_gemm_h<D_, H_, true >,
                         cudaFuncAttributeMaxDynamicSharedMemorySize, GEMM_SMEM_BYTES);
    cudaFuncSetAttribute(moe_gemm_h<H_, O_, false>,
                         cudaFuncAttributeMaxDynamicSharedMemorySize, GEMM_SMEM_BYTES);

    // 1: router (zeroes out); 2: setup; 3: prep (gather + both transposes)
    router_kernel<<<B_ / 8, 256>>>(x, gw, gb, out);
    setup_kernel<<<1, 256>>>();
    prep1_kernel<<<GATHER_BLOCKS + W1T_BLOCKS + W2T_BLOCKS, 256>>>(x, w1, w2);
    // 4: GEMM1 (ncu capture slot); 5: GEMM2; 6: aux
    moe_gemm_h<D_, H_, true ><<<dim3(H_ / 128, NTILES), 256, GEMM_SMEM_BYTES>>>(p_xa, p_w1t, b1, out);
    moe_gemm_h<H_, O_, false><<<dim3(O_ / 128, NTILES), 256, GEMM_SMEM_BYTES>>>(p_h, p_w2t, b2, out);
    aux_kernel<<<1, 256>>>(out, out_size - 1);
}